// round 5
// baseline (speedup 1.0000x reference)
#include <cuda_runtime.h>
#include <cuda_bf16.h>
#include <math.h>
#include <cstdint>

#define SEQ   2048
#define NH    16
#define NKV   2
#define HD    128
#define QSZ   (NH * HD)            // 2048
#define KVSZ  (NKV * HD)           // 256
#define QKVN  (QSZ + 2 * KVSZ)     // 2560
#define HID   2048
#define GROUPS (NH / NKV)          // 8

// ---------------- scratch (device globals; no allocs allowed) ----------------
__device__ float g_qkv[SEQ * QKVN];
__device__ float g_q[NH * SEQ * HD];
__device__ float g_k[NKV * SEQ * HD];
__device__ float g_v[NKV * SEQ * HD];
__device__ float g_attn[SEQ * QSZ];
__device__ int   g_pos[SEQ];
__device__ int   g_segstart[SEQ];
__device__ float g_invf[HD / 2];

// bf16 hi/lo split buffers
__device__ __nv_bfloat16 g_xh[SEQ * HID];
__device__ __nv_bfloat16 g_xl[SEQ * HID];
__device__ __nv_bfloat16 g_wqkvT_h[QKVN * HID];
__device__ __nv_bfloat16 g_wqkvT_l[QKVN * HID];
__device__ __nv_bfloat16 g_woT_h[HID * QSZ];
__device__ __nv_bfloat16 g_woT_l[HID * QSZ];

__device__ __forceinline__ uint32_t smem_u32(const void* p) {
    uint32_t a;
    asm("{ .reg .u64 t; cvta.to.shared.u64 t, %1; cvt.u32.u64 %0, t; }" : "=r"(a) : "l"(p));
    return a;
}

#define CP_ASYNC16(smem_addr, gptr) \
    asm volatile("cp.async.cg.shared.global [%0], [%1], 16;\n" \
        :: "r"((uint32_t)(smem_addr)), "l"(gptr))

__device__ __forceinline__ void ldmatrix_x4(uint32_t* r, uint32_t addr) {
    asm volatile("ldmatrix.sync.aligned.m8n8.x4.shared.b16 {%0,%1,%2,%3}, [%4];"
        : "=r"(r[0]), "=r"(r[1]), "=r"(r[2]), "=r"(r[3]) : "r"(addr));
}

__device__ __forceinline__ void mma_bf16(float* c, const uint32_t* a, uint32_t b0, uint32_t b1) {
    asm volatile(
        "mma.sync.aligned.m16n8k16.row.col.f32.bf16.bf16.f32 "
        "{%0,%1,%2,%3}, {%4,%5,%6,%7}, {%8,%9}, {%0,%1,%2,%3};"
        : "+f"(c[0]), "+f"(c[1]), "+f"(c[2]), "+f"(c[3])
        : "r"(a[0]), "r"(a[1]), "r"(a[2]), "r"(a[3]), "r"(b0), "r"(b1));
}

// ---------------- prep: decode positions (int32/int64), seg scan ----------------
__global__ void prep_kernel(const int* __restrict__ words) {
    __shared__ int chunk_last[256];
    int tid = threadIdx.x;
    int is64 = (words[1] == 0) ? 1 : 0;

    if (tid < HD / 2) {
        g_invf[tid] = (float)(1.0 / pow(1.0e6, (double)(2 * tid) / (double)HD));
    }

    int base = tid * 8;
    int local_pos[8];
    int run = -1;
    #pragma unroll
    for (int e = 0; e < 8; e++) {
        int i = base + e;
        int p = is64 ? words[2 * i] : words[i];
        if (p < 0) p = 0;
        local_pos[e] = p;
        g_pos[i] = p;
        if (p == 0) run = i;
    }
    chunk_last[tid] = run;
    __syncthreads();
    if (tid == 0) {
        int m = -1;
        for (int t = 0; t < 256; t++) {
            int c = chunk_last[t];
            chunk_last[t] = m;
            m = max(m, c);
        }
    }
    __syncthreads();
    int m = chunk_last[tid];
    #pragma unroll
    for (int e = 0; e < 8; e++) {
        int i = base + e;
        if (local_pos[e] == 0) m = i;
        g_segstart[i] = max(m, 0);
    }
}

// ---------------- fp32 -> bf16 hi/lo (row-major, vectorized) ----------------
__global__ void split_rowmajor(const float4* __restrict__ X,
                               __nv_bfloat162* __restrict__ Hh,
                               __nv_bfloat162* __restrict__ Hl, int n4) {
    int i = blockIdx.x * blockDim.x + threadIdx.x;
    if (i >= n4) return;
    float4 v = X[i];
    __nv_bfloat16 hx = __float2bfloat16(v.x);
    __nv_bfloat16 hy = __float2bfloat16(v.y);
    __nv_bfloat16 hz = __float2bfloat16(v.z);
    __nv_bfloat16 hw = __float2bfloat16(v.w);
    Hh[2 * i]     = __nv_bfloat162(hx, hy);
    Hh[2 * i + 1] = __nv_bfloat162(hz, hw);
    __nv_bfloat16 lx = __float2bfloat16(v.x - __bfloat162float(hx));
    __nv_bfloat16 ly = __float2bfloat16(v.y - __bfloat162float(hy));
    __nv_bfloat16 lz = __float2bfloat16(v.z - __bfloat162float(hz));
    __nv_bfloat16 lw = __float2bfloat16(v.w - __bfloat162float(hw));
    Hl[2 * i]     = __nv_bfloat162(lx, ly);
    Hl[2 * i + 1] = __nv_bfloat162(lz, lw);
}

// ---------------- fp32 W[K][N] -> bf16 hi/lo W^T [N][K] ----------------
__global__ void split_transpose(const float* __restrict__ W,
                                __nv_bfloat16* __restrict__ Th,
                                __nv_bfloat16* __restrict__ Tl, int K, int N) {
    __shared__ float t[32][33];
    int n0 = blockIdx.x * 32, k0 = blockIdx.y * 32;
    int tx = threadIdx.x, ty = threadIdx.y;   // (32, 8)
    #pragma unroll
    for (int i = 0; i < 32; i += 8)
        t[ty + i][tx] = W[(size_t)(k0 + ty + i) * N + n0 + tx];
    __syncthreads();
    #pragma unroll
    for (int i = 0; i < 32; i += 8) {
        float v = t[tx][ty + i];
        __nv_bfloat16 h = __float2bfloat16(v);
        float lo = v - __bfloat162float(h);
        size_t o = (size_t)(n0 + ty + i) * K + k0 + tx;
        Th[o] = h;
        Tl[o] = __float2bfloat16(lo);
    }
}

// ====== HMMA GEMM: C[M,N](f32) = A * B^T, bf16 hi/lo 3-term split ============
// A: [M][K] K-major; B: [N][K] K-major. Tile 128x128, BK=32, 8 warps (64x32).
#define BK      32
#define LDS_EL  40          // padded row stride in bf16 elements (80 B)
#define STAGE_B (4 * 128 * LDS_EL * 2)   // 40960 B per stage

__global__ __launch_bounds__(256)
void gemm_mma(const __nv_bfloat16* __restrict__ Ah, const __nv_bfloat16* __restrict__ Al,
              const __nv_bfloat16* __restrict__ Bh, const __nv_bfloat16* __restrict__ Bl,
              const float* __restrict__ bias, float* __restrict__ C,
              int M, int N, int K)
{
    extern __shared__ char dsm[];
    uint32_t sbase = smem_u32(dsm);

    int tid  = threadIdx.x;
    int wid  = tid >> 5;
    int lane = tid & 31;
    int bx = blockIdx.x, by = blockIdx.y;

    int wm = (wid >> 2) * 64;       // warp row offset in tile
    int wn = (wid & 3) * 32;        // warp col offset in tile

    size_t arow0 = (size_t)by * 128;
    size_t brow0 = (size_t)bx * 128;

    // per-thread load coords: 512 16B-chunks per array per stage, 2 per thread
    int c0 = tid, c1 = tid + 256;
    int lr0 = c0 >> 2, lq0 = c0 & 3;
    int lr1 = c1 >> 2, lq1 = c1 & 3;
    uint32_t so0 = (uint32_t)(lr0 * LDS_EL * 2 + lq0 * 16);
    uint32_t so1 = (uint32_t)(lr1 * LDS_EL * 2 + lq1 * 16);

    float acc[4][4][4];
    #pragma unroll
    for (int i = 0; i < 4; i++)
        #pragma unroll
        for (int j = 0; j < 4; j++)
            #pragma unroll
            for (int e = 0; e < 4; e++) acc[i][j][e] = 0.f;

    int nchunks = K / BK;

    // prefetch chunk 0 into stage 0
    {
        int koff = 0;
        uint32_t st = sbase;
        CP_ASYNC16(st +             so0, Ah + (arow0 + lr0) * (size_t)K + koff + lq0 * 8);
        CP_ASYNC16(st +             so1, Ah + (arow0 + lr1) * (size_t)K + koff + lq1 * 8);
        CP_ASYNC16(st + 10240     + so0, Al + (arow0 + lr0) * (size_t)K + koff + lq0 * 8);
        CP_ASYNC16(st + 10240     + so1, Al + (arow0 + lr1) * (size_t)K + koff + lq1 * 8);
        CP_ASYNC16(st + 20480     + so0, Bh + (brow0 + lr0) * (size_t)K + koff + lq0 * 8);
        CP_ASYNC16(st + 20480     + so1, Bh + (brow0 + lr1) * (size_t)K + koff + lq1 * 8);
        CP_ASYNC16(st + 30720     + so0, Bl + (brow0 + lr0) * (size_t)K + koff + lq0 * 8);
        CP_ASYNC16(st + 30720     + so1, Bl + (brow0 + lr1) * (size_t)K + koff + lq1 * 8);
        asm volatile("cp.async.commit_group;\n" ::: "memory");
    }

    // lane-invariant ldmatrix sub-addresses
    int a_row = lane & 15;
    int a_k8  = (lane >> 4) & 1;          // which k-8 half
    int b_row = (lane & 7) + ((lane >> 4) << 3);   // n within 16 (two 8-blocks)
    int b_k8  = (lane >> 3) & 1;

    for (int kc = 0; kc < nchunks; kc++) {
        if (kc + 1 < nchunks) {
            int koff = (kc + 1) * BK;
            uint32_t st = sbase + ((kc + 1) & 1) * STAGE_B;
            CP_ASYNC16(st +         so0, Ah + (arow0 + lr0) * (size_t)K + koff + lq0 * 8);
            CP_ASYNC16(st +         so1, Ah + (arow0 + lr1) * (size_t)K + koff + lq1 * 8);
            CP_ASYNC16(st + 10240 + so0, Al + (arow0 + lr0) * (size_t)K + koff + lq0 * 8);
            CP_ASYNC16(st + 10240 + so1, Al + (arow0 + lr1) * (size_t)K + koff + lq1 * 8);
            CP_ASYNC16(st + 20480 + so0, Bh + (brow0 + lr0) * (size_t)K + koff + lq0 * 8);
            CP_ASYNC16(st + 20480 + so1, Bh + (brow0 + lr1) * (size_t)K + koff + lq1 * 8);
            CP_ASYNC16(st + 30720 + so0, Bl + (brow0 + lr0) * (size_t)K + koff + lq0 * 8);
            CP_ASYNC16(st + 30720 + so1, Bl + (brow0 + lr1) * (size_t)K + koff + lq1 * 8);
        }
        asm volatile("cp.async.commit_group;\n" ::: "memory");
        asm volatile("cp.async.wait_group 1;\n" ::: "memory");
        __syncthreads();

        uint32_t st  = sbase + (kc & 1) * STAGE_B;
        uint32_t sAh = st, sAl = st + 10240, sBh = st + 20480, sBl = st + 30720;

        #pragma unroll
        for (int ks = 0; ks < 2; ks++) {
            int k0 = ks * 16;
            uint32_t ah[4][4], al[4][4];
            #pragma unroll
            for (int mi = 0; mi < 4; mi++) {
                uint32_t off = (uint32_t)((wm + mi * 16 + a_row) * LDS_EL + k0 + a_k8 * 8) * 2;
                ldmatrix_x4(ah[mi], sAh + off);
                ldmatrix_x4(al[mi], sAl + off);
            }
            uint32_t bh[2][4], bl[2][4];
            #pragma unroll
            for (int nb = 0; nb < 2; nb++) {
                uint32_t off = (uint32_t)((wn + nb * 16 + b_row) * LDS_EL + k0 + b_k8 * 8) * 2;
                ldmatrix_x4(bh[nb], sBh + off);
                ldmatrix_x4(bl[nb], sBl + off);
            }
            #pragma unroll
            for (int mi = 0; mi < 4; mi++)
                #pragma unroll
                for (int ni = 0; ni < 4; ni++) {
                    uint32_t h0 = bh[ni >> 1][(ni & 1) * 2];
                    uint32_t h1 = bh[ni >> 1][(ni & 1) * 2 + 1];
                    uint32_t l0 = bl[ni >> 1][(ni & 1) * 2];
                    uint32_t l1 = bl[ni >> 1][(ni & 1) * 2 + 1];
                    mma_bf16(acc[mi][ni], ah[mi], h0, h1);
                    mma_bf16(acc[mi][ni], ah[mi], l0, l1);
                    mma_bf16(acc[mi][ni], al[mi], h0, h1);
                }
        }
        __syncthreads();
    }

    // epilogue: write C (+bias)
    int trow = lane >> 2;
    int tcol = (lane & 3) * 2;
    #pragma unroll
    for (int mi = 0; mi < 4; mi++) {
        #pragma unroll
        for (int h = 0; h < 2; h++) {
            size_t row = arow0 + wm + mi * 16 + trow + h * 8;
            float* crow = C + row * (size_t)N + brow0 + wn;
            #pragma unroll
            for (int ni = 0; ni < 4; ni++) {
                int col = ni * 8 + tcol;
                float2 o;
                o.x = acc[mi][ni][2 * h];
                o.y = acc[mi][ni][2 * h + 1];
                if (bias) {
                    o.x += bias[brow0 + wn + col];
                    o.y += bias[brow0 + wn + col + 1];
                }
                *(float2*)(crow + col) = o;
            }
        }
    }
}

// ---------------- RoPE + split into head-major q/k/v ----------------
__global__ void rope_split_kernel() {
    const int NQ = SEQ * NH * (HD / 2);
    const int NK = SEQ * NKV * (HD / 2);
    const int NV = SEQ * NKV * (HD / 4);
    int idx = blockIdx.x * blockDim.x + threadIdx.x;
    if (idx < NQ) {
        int s   = idx / (NH * (HD / 2));
        int rem = idx % (NH * (HD / 2));
        int h = rem >> 6, j = rem & 63;
        float freq = (float)g_pos[s] * g_invf[j];
        float sn, cs;
        sincosf(freq, &sn, &cs);
        const float* row = g_qkv + (size_t)s * QKVN + h * HD + 2 * j;
        float x1 = row[0], x2 = row[1];
        const float qscale = 0.08838834764831845f;
        float* dst = g_q + ((size_t)h * SEQ + s) * HD + 2 * j;
        dst[0] = (x1 * cs - x2 * sn) * qscale;
        dst[1] = (x1 * sn + x2 * cs) * qscale;
        return;
    }
    idx -= NQ;
    if (idx < NK) {
        int s   = idx / (NKV * (HD / 2));
        int rem = idx % (NKV * (HD / 2));
        int h = rem >> 6, j = rem & 63;
        float freq = (float)g_pos[s] * g_invf[j];
        float sn, cs;
        sincosf(freq, &sn, &cs);
        const float* row = g_qkv + (size_t)s * QKVN + QSZ + h * HD + 2 * j;
        float x1 = row[0], x2 = row[1];
        float* dst = g_k + ((size_t)h * SEQ + s) * HD + 2 * j;
        dst[0] = x1 * cs - x2 * sn;
        dst[1] = x1 * sn + x2 * cs;
        return;
    }
    idx -= NK;
    if (idx < NV) {
        int s = idx / (KVSZ / 4);
        int w = idx % (KVSZ / 4);
        int h = w >> 5;
        int d = (w * 4) & (HD - 1);
        float4 v = *(const float4*)(g_qkv + (size_t)s * QKVN + QSZ + KVSZ + w * 4);
        *(float4*)(g_v + ((size_t)h * SEQ + s) * HD + d) = v;
    }
}

// ---------------- flash attention: 64q x 64k tiles, online softmax ----------------
#define QT 64
#define KT 64
#define QPAD 132
#define SPAD 65

__global__ __launch_bounds__(256) void flash_attn_kernel() {
    extern __shared__ float sm[];
    float* Qs   = sm;
    float* Ks   = Qs + 64 * QPAD;
    float* Vs   = Ks + 64 * QPAD;
    float* Ss   = Vs + 64 * HD;
    float* mbuf = Ss + 64 * SPAD;
    float* lbuf = mbuf + 64;
    float* abuf = lbuf + 64;
    float* red  = abuf + 64;
    __shared__ int s_ktmin;

    int tid = threadIdx.x;
    int tx = tid & 15, ty = tid >> 4;
    int qt = gridDim.x - 1 - blockIdx.x;     // heavy tiles first
    int h  = blockIdx.y;
    int kvh = h / GROUPS;
    int q0 = qt * QT;

    const float* qg = g_q + ((size_t)h * SEQ + q0) * HD;
    for (int it = tid; it < QT * HD; it += 256) {
        int r = it >> 7, c = it & 127;
        Qs[r * QPAD + c] = qg[it];
    }
    if (tid < QT) { mbuf[tid] = -1e30f; lbuf[tid] = 0.f; }
    if (tid == 0) {
        int mn = 0x7fffffff;
        for (int r = 0; r < QT; r++) mn = min(mn, g_segstart[q0 + r]);
        s_ktmin = mn >> 6;
    }
    float acc[4][8];
    #pragma unroll
    for (int i = 0; i < 4; i++)
        #pragma unroll
        for (int j = 0; j < 8; j++) acc[i][j] = 0.f;
    __syncthreads();

    int r0 = ty * 4;
    int c0 = tx * 4;

    for (int kt = s_ktmin; kt <= qt; kt++) {
        const float* kg = g_k + ((size_t)kvh * SEQ + kt * KT) * HD;
        const float* vg = g_v + ((size_t)kvh * SEQ + kt * KT) * HD;
        for (int it = tid; it < KT * HD; it += 256) {
            int r = it >> 7, c = it & 127;
            Ks[r * QPAD + c] = kg[it];
            Vs[r * HD + c]   = vg[it];
        }
        __syncthreads();

        float sa[4][4];
        #pragma unroll
        for (int i = 0; i < 4; i++)
            #pragma unroll
            for (int j = 0; j < 4; j++) sa[i][j] = 0.f;
        #pragma unroll 2
        for (int kk = 0; kk < HD; kk += 4) {
            float4 a[4], b[4];
            #pragma unroll
            for (int i = 0; i < 4; i++) a[i] = *(float4*)&Qs[(r0 + i) * QPAD + kk];
            #pragma unroll
            for (int j = 0; j < 4; j++) b[j] = *(float4*)&Ks[(c0 + j) * QPAD + kk];
            #pragma unroll
            for (int i = 0; i < 4; i++)
                #pragma unroll
                for (int j = 0; j < 4; j++) {
                    sa[i][j] = fmaf(a[i].x, b[j].x, sa[i][j]);
                    sa[i][j] = fmaf(a[i].y, b[j].y, sa[i][j]);
                    sa[i][j] = fmaf(a[i].z, b[j].z, sa[i][j]);
                    sa[i][j] = fmaf(a[i].w, b[j].w, sa[i][j]);
                }
        }
        #pragma unroll
        for (int i = 0; i < 4; i++)
            #pragma unroll
            for (int j = 0; j < 4; j++)
                Ss[(r0 + i) * SPAD + c0 + j] = sa[i][j];
        __syncthreads();

        {
            int r = tid >> 2, qd = tid & 3;
            int sg = q0 + r;
            int tstart = g_segstart[sg];
            float mx = -1e30f;
            int cb = qd * 16;
            #pragma unroll
            for (int c = 0; c < 16; c++) {
                int t = kt * KT + cb + c;
                if (t <= sg && t >= tstart) mx = fmaxf(mx, Ss[r * SPAD + cb + c]);
            }
            red[r * 4 + qd] = mx;
        }
        __syncthreads();
        if (tid < QT) {
            int r = tid;
            float mx = fmaxf(fmaxf(red[r*4], red[r*4+1]), fmaxf(red[r*4+2], red[r*4+3]));
            float mold = mbuf[r];
            float mnew = fmaxf(mold, mx);
            abuf[r] = __expf(mold - mnew);
            mbuf[r] = mnew;
        }
        __syncthreads();
        {
            int r = tid >> 2, qd = tid & 3;
            int sg = q0 + r;
            int tstart = g_segstart[sg];
            float mnew = mbuf[r];
            float sum = 0.f;
            int cb = qd * 16;
            #pragma unroll
            for (int c = 0; c < 16; c++) {
                int t = kt * KT + cb + c;
                float p = 0.f;
                if (t <= sg && t >= tstart) p = __expf(Ss[r * SPAD + cb + c] - mnew);
                Ss[r * SPAD + cb + c] = p;
                sum += p;
            }
            red[r * 4 + qd] = sum;
        }
        __syncthreads();
        if (tid < QT) {
            int r = tid;
            lbuf[r] = lbuf[r] * abuf[r] + red[r*4] + red[r*4+1] + red[r*4+2] + red[r*4+3];
        }
        __syncthreads();

        float al[4];
        #pragma unroll
        for (int i = 0; i < 4; i++) al[i] = abuf[r0 + i];
        #pragma unroll
        for (int i = 0; i < 4; i++)
            #pragma unroll
            for (int j = 0; j < 8; j++) acc[i][j] *= al[i];
        int oc = tx * 8;
        for (int kk = 0; kk < KT; kk++) {
            float p[4];
            #pragma unroll
            for (int i = 0; i < 4; i++) p[i] = Ss[(r0 + i) * SPAD + kk];
            float4 v0 = *(float4*)&Vs[kk * HD + oc];
            float4 v1 = *(float4*)&Vs[kk * HD + oc + 4];
            #pragma unroll
            for (int i = 0; i < 4; i++) {
                acc[i][0] = fmaf(p[i], v0.x, acc[i][0]);
                acc[i][1] = fmaf(p[i], v0.y, acc[i][1]);
                acc[i][2] = fmaf(p[i], v0.z, acc[i][2]);
                acc[i][3] = fmaf(p[i], v0.w, acc[i][3]);
                acc[i][4] = fmaf(p[i], v1.x, acc[i][4]);
                acc[i][5] = fmaf(p[i], v1.y, acc[i][5]);
                acc[i][6] = fmaf(p[i], v1.z, acc[i][6]);
                acc[i][7] = fmaf(p[i], v1.w, acc[i][7]);
            }
        }
        __syncthreads();
    }

    #pragma unroll
    for (int i = 0; i < 4; i++) {
        float l = lbuf[r0 + i];
        float rn = (l > 0.f) ? 1.f / l : 0.f;
        int row = q0 + r0 + i;
        float* dst = g_attn + (size_t)row * QSZ + h * HD + tx * 8;
        float4 o0, o1;
        o0.x = acc[i][0]*rn; o0.y = acc[i][1]*rn; o0.z = acc[i][2]*rn; o0.w = acc[i][3]*rn;
        o1.x = acc[i][4]*rn; o1.y = acc[i][5]*rn; o1.z = acc[i][6]*rn; o1.w = acc[i][7]*rn;
        *(float4*)(dst)     = o0;
        *(float4*)(dst + 4) = o1;
    }
}

// ---------------- launch ----------------
extern "C" void kernel_launch(void* const* d_in, const int* in_sizes, int n_in,
                              void* d_out, int out_size) {
    const float* hidden = (const float*)d_in[0];
    const int*   posw   = (const int*)d_in[1];
    const float* w_qkv  = (const float*)d_in[2];
    const float* b_qkv  = (const float*)d_in[3];
    const float* w_o    = (const float*)d_in[4];
    float* out = (float*)d_out;

    void *p_qkv = nullptr, *p_attn = nullptr;
    void *p_xh = nullptr, *p_xl = nullptr;
    void *p_wqh = nullptr, *p_wql = nullptr, *p_woh = nullptr, *p_wol = nullptr;
    cudaGetSymbolAddress(&p_qkv, g_qkv);
    cudaGetSymbolAddress(&p_attn, g_attn);
    cudaGetSymbolAddress(&p_xh, g_xh);
    cudaGetSymbolAddress(&p_xl, g_xl);
    cudaGetSymbolAddress(&p_wqh, g_wqkvT_h);
    cudaGetSymbolAddress(&p_wql, g_wqkvT_l);
    cudaGetSymbolAddress(&p_woh, g_woT_h);
    cudaGetSymbolAddress(&p_wol, g_woT_l);

    const int gemm_smem = 2 * STAGE_B;   // 81920
    cudaFuncSetAttribute(gemm_mma, cudaFuncAttributeMaxDynamicSharedMemorySize, gemm_smem);

    prep_kernel<<<1, 256>>>(posw);

    split_rowmajor<<<(SEQ * HID / 4 + 255) / 256, 256>>>(
        (const float4*)hidden, (__nv_bfloat162*)p_xh, (__nv_bfloat162*)p_xl, SEQ * HID / 4);
    split_transpose<<<dim3(QKVN / 32, HID / 32), dim3(32, 8)>>>(
        w_qkv, (__nv_bfloat16*)p_wqh, (__nv_bfloat16*)p_wql, HID, QKVN);
    split_transpose<<<dim3(HID / 32, QSZ / 32), dim3(32, 8)>>>(
        w_o, (__nv_bfloat16*)p_woh, (__nv_bfloat16*)p_wol, QSZ, HID);

    gemm_mma<<<dim3(QKVN / 128, SEQ / 128), 256, gemm_smem>>>(
        (const __nv_bfloat16*)p_xh, (const __nv_bfloat16*)p_xl,
        (const __nv_bfloat16*)p_wqh, (const __nv_bfloat16*)p_wql,
        b_qkv, (float*)p_qkv, SEQ, QKVN, HID);

    int total = SEQ * NH * (HD / 2) + SEQ * NKV * (HD / 2) + SEQ * NKV * (HD / 4);
    rope_split_kernel<<<(total + 255) / 256, 256>>>();

    size_t fa_smem = (size_t)(64 * QPAD * 2 + 64 * HD + 64 * SPAD + 64 * 3 + 256) * sizeof(float);
    cudaFuncSetAttribute(flash_attn_kernel,
                         cudaFuncAttributeMaxDynamicSharedMemorySize, (int)fa_smem);
    flash_attn_kernel<<<dim3(SEQ / QT, NH), 256, fa_smem>>>();

    split_rowmajor<<<(SEQ * QSZ / 4 + 255) / 256, 256>>>(
        (const float4*)p_attn, (__nv_bfloat162*)p_xh, (__nv_bfloat162*)p_xl, SEQ * QSZ / 4);
    gemm_mma<<<dim3(HID / 128, SEQ / 128), 256, gemm_smem>>>(
        (const __nv_bfloat16*)p_xh, (const __nv_bfloat16*)p_xl,
        (const __nv_bfloat16*)p_woh, (const __nv_bfloat16*)p_wol,
        nullptr, out, SEQ, HID, QSZ);
}

// round 6
// speedup vs baseline: 2.2935x; 2.2935x over previous
#include <cuda_runtime.h>
#include <cuda_bf16.h>
#include <math.h>
#include <cstdint>

#define SEQ   2048
#define NH    16
#define NKV   2
#define HD    128
#define QSZ   (NH * HD)            // 2048
#define KVSZ  (NKV * HD)           // 256
#define QKVN  (QSZ + 2 * KVSZ)     // 2560
#define HID   2048
#define GROUPS (NH / NKV)          // 8

// ---------------- scratch (device globals; no allocs allowed) ----------------
__device__ float g_qkv[SEQ * QKVN];
__device__ float g_attn[SEQ * QSZ];
__device__ int   g_pos[SEQ];
__device__ int   g_segstart[SEQ];
__device__ float g_invf[HD / 2];

// bf16 hi/lo split attention operands
__device__ __nv_bfloat16 g_qh[NH * SEQ * HD];     // [h][s][d]
__device__ __nv_bfloat16 g_ql[NH * SEQ * HD];
__device__ __nv_bfloat16 g_kh[NKV * SEQ * HD];    // [kvh][s][d]
__device__ __nv_bfloat16 g_kl[NKV * SEQ * HD];
__device__ __nv_bfloat16 g_vTh[NKV * HD * SEQ];   // [kvh][d][s]  (transposed)
__device__ __nv_bfloat16 g_vTl[NKV * HD * SEQ];

__device__ __forceinline__ uint32_t smem_u32(const void* p) {
    uint32_t a;
    asm("{ .reg .u64 t; cvta.to.shared.u64 t, %1; cvt.u32.u64 %0, t; }" : "=r"(a) : "l"(p));
    return a;
}

#define CP_ASYNC16(smem_addr, gptr) \
    asm volatile("cp.async.cg.shared.global [%0], [%1], 16;\n" \
        :: "r"((uint32_t)(smem_addr)), "l"(gptr))

__device__ __forceinline__ void ldmatrix_x4(uint32_t* r, uint32_t addr) {
    asm volatile("ldmatrix.sync.aligned.m8n8.x4.shared.b16 {%0,%1,%2,%3}, [%4];"
        : "=r"(r[0]), "=r"(r[1]), "=r"(r[2]), "=r"(r[3]) : "r"(addr));
}

__device__ __forceinline__ void mma_bf16(float* c, const uint32_t* a, uint32_t b0, uint32_t b1) {
    asm volatile(
        "mma.sync.aligned.m16n8k16.row.col.f32.bf16.bf16.f32 "
        "{%0,%1,%2,%3}, {%4,%5,%6,%7}, {%8,%9}, {%0,%1,%2,%3};"
        : "+f"(c[0]), "+f"(c[1]), "+f"(c[2]), "+f"(c[3])
        : "r"(a[0]), "r"(a[1]), "r"(a[2]), "r"(a[3]), "r"(b0), "r"(b1));
}

// pack two fp32 into bf16x2 (lo in low half)
__device__ __forceinline__ uint32_t pack_bf16(float lo, float hi) {
    uint32_t r;
    asm("cvt.rn.bf16x2.f32 %0, %1, %2;" : "=r"(r) : "f"(hi), "f"(lo));
    return r;
}

// ---------------- prep: decode positions (int32/int64), seg scan ----------------
__global__ void prep_kernel(const int* __restrict__ words) {
    __shared__ int chunk_last[256];
    int tid = threadIdx.x;
    int is64 = (words[1] == 0) ? 1 : 0;

    if (tid < HD / 2) {
        g_invf[tid] = (float)(1.0 / pow(1.0e6, (double)(2 * tid) / (double)HD));
    }

    int base = tid * 8;
    int local_pos[8];
    int run = -1;
    #pragma unroll
    for (int e = 0; e < 8; e++) {
        int i = base + e;
        int p = is64 ? words[2 * i] : words[i];
        if (p < 0) p = 0;
        local_pos[e] = p;
        g_pos[i] = p;
        if (p == 0) run = i;
    }
    chunk_last[tid] = run;
    __syncthreads();
    if (tid == 0) {
        int m = -1;
        for (int t = 0; t < 256; t++) {
            int c = chunk_last[t];
            chunk_last[t] = m;
            m = max(m, c);
        }
    }
    __syncthreads();
    int m = chunk_last[tid];
    #pragma unroll
    for (int e = 0; e < 8; e++) {
        int i = base + e;
        if (local_pos[e] == 0) m = i;
        g_segstart[i] = max(m, 0);
    }
}

// ---------------- SGEMM: C[M,N] = A[M,K] @ B[K,N] (+bias), 128x128x8, 8x8 micro ----------------
__global__ __launch_bounds__(256) void sgemm_bias(
    const float* __restrict__ A, const float* __restrict__ B,
    const float* __restrict__ bias, float* __restrict__ C,
    int M, int N, int K)
{
    __shared__ float As[8][128];
    __shared__ float Bs[8][128];
    int tid = threadIdx.x;
    int bx = blockIdx.x, by = blockIdx.y;
    int tx = tid & 15, ty = tid >> 4;

    int arow = tid >> 1;
    int acol = (tid & 1) * 4;
    int brow = tid >> 5;
    int bcol = (tid & 31) * 4;

    const float* Aptr = A + (size_t)(by * 128 + arow) * K + acol;
    const float* Bptr = B + (size_t)brow * N + bx * 128 + bcol;

    float acc[8][8];
    #pragma unroll
    for (int i = 0; i < 8; i++)
        #pragma unroll
        for (int j = 0; j < 8; j++) acc[i][j] = 0.f;

    for (int k0 = 0; k0 < K; k0 += 8) {
        float4 a = *(const float4*)(Aptr + k0);
        As[acol + 0][arow] = a.x;
        As[acol + 1][arow] = a.y;
        As[acol + 2][arow] = a.z;
        As[acol + 3][arow] = a.w;
        float4 b = *(const float4*)(Bptr + (size_t)k0 * N);
        *(float4*)&Bs[brow][bcol] = b;
        __syncthreads();
        #pragma unroll
        for (int kk = 0; kk < 8; kk++) {
            float ar[8], br[8];
            float4 a0 = *(float4*)&As[kk][ty * 8];
            float4 a1 = *(float4*)&As[kk][ty * 8 + 4];
            float4 b0 = *(float4*)&Bs[kk][tx * 8];
            float4 b1 = *(float4*)&Bs[kk][tx * 8 + 4];
            ar[0]=a0.x; ar[1]=a0.y; ar[2]=a0.z; ar[3]=a0.w;
            ar[4]=a1.x; ar[5]=a1.y; ar[6]=a1.z; ar[7]=a1.w;
            br[0]=b0.x; br[1]=b0.y; br[2]=b0.z; br[3]=b0.w;
            br[4]=b1.x; br[5]=b1.y; br[6]=b1.z; br[7]=b1.w;
            #pragma unroll
            for (int i = 0; i < 8; i++)
                #pragma unroll
                for (int j = 0; j < 8; j++)
                    acc[i][j] = fmaf(ar[i], br[j], acc[i][j]);
        }
        __syncthreads();
    }

    float bv[8];
    if (bias) {
        float4 q0 = *(const float4*)(bias + bx * 128 + tx * 8);
        float4 q1 = *(const float4*)(bias + bx * 128 + tx * 8 + 4);
        bv[0]=q0.x; bv[1]=q0.y; bv[2]=q0.z; bv[3]=q0.w;
        bv[4]=q1.x; bv[5]=q1.y; bv[6]=q1.z; bv[7]=q1.w;
    } else {
        #pragma unroll
        for (int j = 0; j < 8; j++) bv[j] = 0.f;
    }

    #pragma unroll
    for (int i = 0; i < 8; i++) {
        int row = by * 128 + ty * 8 + i;
        float* Crow = C + (size_t)row * N + bx * 128 + tx * 8;
        float4 r0, r1;
        r0.x = acc[i][0] + bv[0]; r0.y = acc[i][1] + bv[1];
        r0.z = acc[i][2] + bv[2]; r0.w = acc[i][3] + bv[3];
        r1.x = acc[i][4] + bv[4]; r1.y = acc[i][5] + bv[5];
        r1.z = acc[i][6] + bv[6]; r1.w = acc[i][7] + bv[7];
        *(float4*)(Crow)     = r0;
        *(float4*)(Crow + 4) = r1;
    }
}

// ---------------- RoPE + split into bf16 hi/lo head-major q/k, transposed v ----------------
__global__ void rope_split_kernel() {
    const int NQ = SEQ * NH * (HD / 2);
    const int NK = SEQ * NKV * (HD / 2);
    const int NV = SEQ * NKV * (HD / 4);
    int idx = blockIdx.x * blockDim.x + threadIdx.x;
    if (idx < NQ) {
        int s   = idx / (NH * (HD / 2));
        int rem = idx % (NH * (HD / 2));
        int h = rem >> 6, j = rem & 63;
        float freq = (float)g_pos[s] * g_invf[j];
        float sn, cs;
        sincosf(freq, &sn, &cs);
        const float* row = g_qkv + (size_t)s * QKVN + h * HD + 2 * j;
        float x1 = row[0], x2 = row[1];
        const float qscale = 0.08838834764831845f;
        float re = (x1 * cs - x2 * sn) * qscale;
        float im = (x1 * sn + x2 * cs) * qscale;
        size_t off = ((size_t)h * SEQ + s) * HD + 2 * j;
        __nv_bfloat16 hre = __float2bfloat16(re), him = __float2bfloat16(im);
        __nv_bfloat162 hp; hp.x = hre; hp.y = him;
        *(__nv_bfloat162*)(g_qh + off) = hp;
        __nv_bfloat162 lp;
        lp.x = __float2bfloat16(re - __bfloat162float(hre));
        lp.y = __float2bfloat16(im - __bfloat162float(him));
        *(__nv_bfloat162*)(g_ql + off) = lp;
        return;
    }
    idx -= NQ;
    if (idx < NK) {
        int s   = idx / (NKV * (HD / 2));
        int rem = idx % (NKV * (HD / 2));
        int h = rem >> 6, j = rem & 63;
        float freq = (float)g_pos[s] * g_invf[j];
        float sn, cs;
        sincosf(freq, &sn, &cs);
        const float* row = g_qkv + (size_t)s * QKVN + QSZ + h * HD + 2 * j;
        float x1 = row[0], x2 = row[1];
        float re = x1 * cs - x2 * sn;
        float im = x1 * sn + x2 * cs;
        size_t off = ((size_t)h * SEQ + s) * HD + 2 * j;
        __nv_bfloat16 hre = __float2bfloat16(re), him = __float2bfloat16(im);
        __nv_bfloat162 hp; hp.x = hre; hp.y = him;
        *(__nv_bfloat162*)(g_kh + off) = hp;
        __nv_bfloat162 lp;
        lp.x = __float2bfloat16(re - __bfloat162float(hre));
        lp.y = __float2bfloat16(im - __bfloat162float(him));
        *(__nv_bfloat162*)(g_kl + off) = lp;
        return;
    }
    idx -= NK;
    if (idx < NV) {
        int s = idx / (KVSZ / 4);
        int w = idx % (KVSZ / 4);
        int h = w >> 5;
        int d = (w * 4) & (HD - 1);
        float4 v = *(const float4*)(g_qkv + (size_t)s * QKVN + QSZ + KVSZ + w * 4);
        float vv[4] = {v.x, v.y, v.z, v.w};
        #pragma unroll
        for (int e = 0; e < 4; e++) {
            size_t off = ((size_t)h * HD + d + e) * SEQ + s;
            __nv_bfloat16 hb = __float2bfloat16(vv[e]);
            g_vTh[off] = hb;
            g_vTl[off] = __float2bfloat16(vv[e] - __bfloat162float(hb));
        }
    }
}

// ---------------- flash attention via HMMA (bf16 hi/lo 3-term) ----------------
// CTA: 128 q rows x 64 k keys per iteration; 8 warps, each warp m16 x n64.
// smem (bytes): Qh[128][136]b16 @0 (34816) | Ql @34816
//   stage s in {0,1} @ 69632 + s*71680: Kh[64][136] (17408) | Kl +17408
//                                       Vh[128][72] (18432) @+34816 | Vl @+53248
#define FA_QH    0u
#define FA_QL    34816u
#define FA_ST    69632u
#define FA_STG   71680u
#define FA_KH    0u
#define FA_KL    17408u
#define FA_VH    34816u
#define FA_VL    53248u
#define FA_TOTAL 212992

__global__ __launch_bounds__(256, 1) void flash_mma_kernel() {
    extern __shared__ char sm8[];
    uint32_t sb = smem_u32(sm8);
    __shared__ int s_ktmin;

    int tid = threadIdx.x, wid = tid >> 5, lane = tid & 31;
    int qt = gridDim.x - 1 - blockIdx.x;   // heavy tiles first
    int h = blockIdx.y, kvh = h >> 3;
    int q0 = qt * 128;
    int wm = wid * 16;

    // ldmatrix lane mappings (proven in gemm)
    int a_row = lane & 15;
    int a_k8  = lane >> 4;
    int b_row = (lane & 7) + ((lane >> 4) << 3);
    int b_k8  = (lane >> 3) & 1;
    uint32_t q_off = (uint32_t)((wm + a_row) * 136 + a_k8 * 8) * 2;

    // ---- load Q (hi+lo) into smem ----
    {
        const char* qh = (const char*)(g_qh + ((size_t)h * SEQ + q0) * HD);
        const char* ql = (const char*)(g_ql + ((size_t)h * SEQ + q0) * HD);
        #pragma unroll
        for (int u = 0; u < 8; u++) {
            int c = tid + u * 256;      // 0..2047
            int r = c >> 4, cc = c & 15;
            CP_ASYNC16(sb + FA_QH + r * 272 + cc * 16, qh + r * 256 + cc * 16);
            CP_ASYNC16(sb + FA_QL + r * 272 + cc * 16, ql + r * 256 + cc * 16);
        }
    }
    if (tid == 0) {
        int mn = 0x7fffffff;
        for (int r = 0; r < 128; r++) mn = min(mn, g_segstart[q0 + r]);
        s_ktmin = mn >> 6;
    }

    int sg1 = q0 + wm + (lane >> 2);
    int sg2 = sg1 + 8;
    int ts1 = g_segstart[sg1], ts2 = g_segstart[sg2];

    float o[16][4];
    #pragma unroll
    for (int i = 0; i < 16; i++)
        #pragma unroll
        for (int e = 0; e < 4; e++) o[i][e] = 0.f;
    float m1 = -1e30f, m2 = -1e30f, l1 = 0.f, l2 = 0.f;

    __syncthreads();
    int ktmin = s_ktmin;
    int ktmax = (q0 + 127) >> 6;

    auto prefetch_tile = [&](int kt, int stg) {
        uint32_t st = sb + FA_ST + (uint32_t)stg * FA_STG;
        const char* kh = (const char*)(g_kh + ((size_t)kvh * SEQ + kt * 64) * HD);
        const char* kl = (const char*)(g_kl + ((size_t)kvh * SEQ + kt * 64) * HD);
        const char* vh = (const char*)(g_vTh + (size_t)kvh * HD * SEQ + kt * 64);
        const char* vl = (const char*)(g_vTl + (size_t)kvh * HD * SEQ + kt * 64);
        #pragma unroll
        for (int u = 0; u < 4; u++) {
            int c = tid + u * 256;      // 0..1023
            int r = c >> 4, cc = c & 15;
            CP_ASYNC16(st + FA_KH + r * 272 + cc * 16, kh + r * 256 + cc * 16);
            CP_ASYNC16(st + FA_KL + r * 272 + cc * 16, kl + r * 256 + cc * 16);
            int vr = c >> 3, vc = c & 7;
            CP_ASYNC16(st + FA_VH + vr * 144 + vc * 16, vh + (size_t)vr * 4096 + vc * 16);
            CP_ASYNC16(st + FA_VL + vr * 144 + vc * 16, vl + (size_t)vr * 4096 + vc * 16);
        }
    };

    prefetch_tile(ktmin, 0);
    asm volatile("cp.async.commit_group;\n" ::: "memory");

    for (int kt = ktmin; kt <= ktmax; kt++) {
        int stg = (kt - ktmin) & 1;
        if (kt < ktmax) {
            prefetch_tile(kt + 1, stg ^ 1);
            asm volatile("cp.async.commit_group;\n" ::: "memory");
            asm volatile("cp.async.wait_group 1;\n" ::: "memory");
        } else {
            asm volatile("cp.async.wait_group 0;\n" ::: "memory");
        }
        __syncthreads();
        uint32_t stb = sb + FA_ST + (uint32_t)stg * FA_STG;

        // ---- S = Q K^T : 3-term split ----
        float s[8][4];
        #pragma unroll
        for (int f = 0; f < 8; f++)
            #pragma unroll
            for (int e = 0; e < 4; e++) s[f][e] = 0.f;

        #pragma unroll
        for (int ds = 0; ds < 8; ds++) {
            uint32_t qhf[4], qlf[4];
            ldmatrix_x4(qhf, sb + FA_QH + q_off + ds * 32);
            ldmatrix_x4(qlf, sb + FA_QL + q_off + ds * 32);
            #pragma unroll
            for (int nb = 0; nb < 4; nb++) {
                uint32_t koff = (uint32_t)((nb * 16 + b_row) * 136 + ds * 16 + b_k8 * 8) * 2;
                uint32_t khf[4], klf[4];
                ldmatrix_x4(khf, stb + FA_KH + koff);
                ldmatrix_x4(klf, stb + FA_KL + koff);
                mma_bf16(s[2 * nb],     qhf, khf[0], khf[1]);
                mma_bf16(s[2 * nb],     qhf, klf[0], klf[1]);
                mma_bf16(s[2 * nb],     qlf, khf[0], khf[1]);
                mma_bf16(s[2 * nb + 1], qhf, khf[2], khf[3]);
                mma_bf16(s[2 * nb + 1], qhf, klf[2], klf[3]);
                mma_bf16(s[2 * nb + 1], qlf, khf[2], khf[3]);
            }
        }

        // ---- mask ----
        int colb = kt * 64 + (lane & 3) * 2;
        #pragma unroll
        for (int f = 0; f < 8; f++) {
            int t0 = colb + f * 8, t1 = t0 + 1;
            if (t0 > sg1 || t0 < ts1) s[f][0] = -1e30f;
            if (t1 > sg1 || t1 < ts1) s[f][1] = -1e30f;
            if (t0 > sg2 || t0 < ts2) s[f][2] = -1e30f;
            if (t1 > sg2 || t1 < ts2) s[f][3] = -1e30f;
        }

        // ---- online softmax (rows spread over 4 lanes; shfl xor 1,2) ----
        float mx1 = -1e30f, mx2 = -1e30f;
        #pragma unroll
        for (int f = 0; f < 8; f++) {
            mx1 = fmaxf(mx1, fmaxf(s[f][0], s[f][1]));
            mx2 = fmaxf(mx2, fmaxf(s[f][2], s[f][3]));
        }
        mx1 = fmaxf(mx1, __shfl_xor_sync(0xffffffffu, mx1, 1));
        mx1 = fmaxf(mx1, __shfl_xor_sync(0xffffffffu, mx1, 2));
        mx2 = fmaxf(mx2, __shfl_xor_sync(0xffffffffu, mx2, 1));
        mx2 = fmaxf(mx2, __shfl_xor_sync(0xffffffffu, mx2, 2));
        float mn1 = fmaxf(m1, mx1), mn2 = fmaxf(m2, mx2);
        float a1 = __expf(m1 - mn1), a2 = __expf(m2 - mn2);
        m1 = mn1; m2 = mn2;

        float sum1 = 0.f, sum2 = 0.f;
        #pragma unroll
        for (int f = 0; f < 8; f++) {
            s[f][0] = __expf(s[f][0] - mn1);
            s[f][1] = __expf(s[f][1] - mn1);
            s[f][2] = __expf(s[f][2] - mn2);
            s[f][3] = __expf(s[f][3] - mn2);
            sum1 += s[f][0] + s[f][1];
            sum2 += s[f][2] + s[f][3];
        }
        sum1 += __shfl_xor_sync(0xffffffffu, sum1, 1);
        sum1 += __shfl_xor_sync(0xffffffffu, sum1, 2);
        sum2 += __shfl_xor_sync(0xffffffffu, sum2, 1);
        sum2 += __shfl_xor_sync(0xffffffffu, sum2, 2);
        l1 = l1 * a1 + sum1;
        l2 = l2 * a2 + sum2;

        #pragma unroll
        for (int i = 0; i < 16; i++) {
            o[i][0] *= a1; o[i][1] *= a1;
            o[i][2] *= a2; o[i][3] *= a2;
        }

        // ---- O += P V : P hi/lo from fp32 probs, V hi/lo from smem ----
        #pragma unroll
        for (int kk = 0; kk < 4; kk++) {
            float p0 = s[2 * kk][0],     p1 = s[2 * kk][1];
            float p2 = s[2 * kk][2],     p3 = s[2 * kk][3];
            float p4 = s[2 * kk + 1][0], p5 = s[2 * kk + 1][1];
            float p6 = s[2 * kk + 1][2], p7 = s[2 * kk + 1][3];
            uint32_t ph[4], pl[4];
            ph[0] = pack_bf16(p0, p1);
            ph[1] = pack_bf16(p2, p3);
            ph[2] = pack_bf16(p4, p5);
            ph[3] = pack_bf16(p6, p7);
            pl[0] = pack_bf16(p0 - __bfloat162float(__float2bfloat16(p0)),
                              p1 - __bfloat162float(__float2bfloat16(p1)));
            pl[1] = pack_bf16(p2 - __bfloat162float(__float2bfloat16(p2)),
                              p3 - __bfloat162float(__float2bfloat16(p3)));
            pl[2] = pack_bf16(p4 - __bfloat162float(__float2bfloat16(p4)),
                              p5 - __bfloat162float(__float2bfloat16(p5)));
            pl[3] = pack_bf16(p6 - __bfloat162float(__float2bfloat16(p6)),
                              p7 - __bfloat162float(__float2bfloat16(p7)));
            #pragma unroll
            for (int nb = 0; nb < 8; nb++) {
                uint32_t voff = (uint32_t)((nb * 16 + b_row) * 72 + kk * 16 + b_k8 * 8) * 2;
                uint32_t vhf[4], vlf[4];
                ldmatrix_x4(vhf, stb + FA_VH + voff);
                ldmatrix_x4(vlf, stb + FA_VL + voff);
                mma_bf16(o[2 * nb],     ph, vhf[0], vhf[1]);
                mma_bf16(o[2 * nb],     ph, vlf[0], vlf[1]);
                mma_bf16(o[2 * nb],     pl, vhf[0], vhf[1]);
                mma_bf16(o[2 * nb + 1], ph, vhf[2], vhf[3]);
                mma_bf16(o[2 * nb + 1], ph, vlf[2], vlf[3]);
                mma_bf16(o[2 * nb + 1], pl, vhf[2], vhf[3]);
            }
        }
        __syncthreads();
    }

    // ---- finalize + write ----
    float rn1 = (l1 > 0.f) ? 1.f / l1 : 0.f;
    float rn2 = (l2 > 0.f) ? 1.f / l2 : 0.f;
    int row1 = q0 + wm + (lane >> 2);
    int row2 = row1 + 8;
    #pragma unroll
    for (int nf = 0; nf < 16; nf++) {
        int col = h * HD + nf * 8 + (lane & 3) * 2;
        float2 w1, w2;
        w1.x = o[nf][0] * rn1; w1.y = o[nf][1] * rn1;
        w2.x = o[nf][2] * rn2; w2.y = o[nf][3] * rn2;
        *(float2*)&g_attn[(size_t)row1 * QSZ + col] = w1;
        *(float2*)&g_attn[(size_t)row2 * QSZ + col] = w2;
    }
}

// ---------------- launch ----------------
extern "C" void kernel_launch(void* const* d_in, const int* in_sizes, int n_in,
                              void* d_out, int out_size) {
    const float* hidden = (const float*)d_in[0];
    const int*   posw   = (const int*)d_in[1];
    const float* w_qkv  = (const float*)d_in[2];
    const float* b_qkv  = (const float*)d_in[3];
    const float* w_o    = (const float*)d_in[4];
    float* out = (float*)d_out;

    void *p_qkv = nullptr, *p_attn = nullptr;
    cudaGetSymbolAddress(&p_qkv, g_qkv);
    cudaGetSymbolAddress(&p_attn, g_attn);

    prep_kernel<<<1, 256>>>(posw);

    sgemm_bias<<<dim3(QKVN / 128, SEQ / 128), 256>>>(
        hidden, w_qkv, b_qkv, (float*)p_qkv, SEQ, QKVN, HID);

    int total = SEQ * NH * (HD / 2) + SEQ * NKV * (HD / 2) + SEQ * NKV * (HD / 4);
    rope_split_kernel<<<(total + 255) / 256, 256>>>();

    cudaFuncSetAttribute(flash_mma_kernel,
                         cudaFuncAttributeMaxDynamicSharedMemorySize, FA_TOTAL);
    flash_mma_kernel<<<dim3(SEQ / 128, NH), 256, FA_TOTAL>>>();

    sgemm_bias<<<dim3(HID / 128, SEQ / 128), 256>>>(
        (const float*)p_attn, w_o, nullptr, out, SEQ, HID, QSZ);
}

// round 7
// speedup vs baseline: 4.6603x; 2.0320x over previous
#include <cuda_runtime.h>
#include <cuda_bf16.h>
#include <math.h>
#include <cstdint>

#define SEQ   2048
#define NH    16
#define NKV   2
#define HD    128
#define QSZ   (NH * HD)            // 2048
#define KVSZ  (NKV * HD)           // 256
#define QKVN  (QSZ + 2 * KVSZ)     // 2560
#define HID   2048
#define GROUPS (NH / NKV)          // 8

// ---------------- scratch (device globals; no allocs allowed) ----------------
__device__ float g_qkv[SEQ * QKVN];
__device__ int   g_pos[SEQ];
__device__ int   g_segstart[SEQ];
__device__ float g_invf[HD / 2];

// bf16 hi/lo split operands
__device__ __nv_bfloat16 g_qh[NH * SEQ * HD];     // [h][s][d]
__device__ __nv_bfloat16 g_ql[NH * SEQ * HD];
__device__ __nv_bfloat16 g_kh[NKV * SEQ * HD];    // [kvh][s][d]
__device__ __nv_bfloat16 g_kl[NKV * SEQ * HD];
__device__ __nv_bfloat16 g_vTh[NKV * HD * SEQ];   // [kvh][d][s]  (transposed)
__device__ __nv_bfloat16 g_vTl[NKV * HD * SEQ];
__device__ __nv_bfloat16 g_xh[SEQ * HID];         // activation hi (hidden, then attn out)
__device__ __nv_bfloat16 g_xl[SEQ * HID];
__device__ __nv_bfloat16 g_wqkvT_h[QKVN * HID];   // w_qkv^T  [2560][2048]
__device__ __nv_bfloat16 g_wqkvT_l[QKVN * HID];
__device__ __nv_bfloat16 g_woT_h[HID * QSZ];      // w_o^T    [2048][2048]
__device__ __nv_bfloat16 g_woT_l[HID * QSZ];

__device__ __forceinline__ uint32_t smem_u32(const void* p) {
    uint32_t a;
    asm("{ .reg .u64 t; cvta.to.shared.u64 t, %1; cvt.u32.u64 %0, t; }" : "=r"(a) : "l"(p));
    return a;
}

#define CP_ASYNC16(smem_addr, gptr) \
    asm volatile("cp.async.cg.shared.global [%0], [%1], 16;\n" \
        :: "r"((uint32_t)(smem_addr)), "l"(gptr))

__device__ __forceinline__ void ldmatrix_x4(uint32_t* r, uint32_t addr) {
    asm volatile("ldmatrix.sync.aligned.m8n8.x4.shared.b16 {%0,%1,%2,%3}, [%4];"
        : "=r"(r[0]), "=r"(r[1]), "=r"(r[2]), "=r"(r[3]) : "r"(addr));
}

__device__ __forceinline__ void mma_bf16(float* c, const uint32_t* a, uint32_t b0, uint32_t b1) {
    asm volatile(
        "mma.sync.aligned.m16n8k16.row.col.f32.bf16.bf16.f32 "
        "{%0,%1,%2,%3}, {%4,%5,%6,%7}, {%8,%9}, {%0,%1,%2,%3};"
        : "+f"(c[0]), "+f"(c[1]), "+f"(c[2]), "+f"(c[3])
        : "r"(a[0]), "r"(a[1]), "r"(a[2]), "r"(a[3]), "r"(b0), "r"(b1));
}

__device__ __forceinline__ uint32_t pack_bf16(float lo, float hi) {
    uint32_t r;
    asm("cvt.rn.bf16x2.f32 %0, %1, %2;" : "=r"(r) : "f"(hi), "f"(lo));
    return r;
}

// ---------------- prep: decode positions (int32/int64), seg scan ----------------
__global__ void prep_kernel(const int* __restrict__ words) {
    __shared__ int chunk_last[256];
    int tid = threadIdx.x;
    int is64 = (words[1] == 0) ? 1 : 0;

    if (tid < HD / 2) {
        g_invf[tid] = (float)(1.0 / pow(1.0e6, (double)(2 * tid) / (double)HD));
    }

    int base = tid * 8;
    int local_pos[8];
    int run = -1;
    #pragma unroll
    for (int e = 0; e < 8; e++) {
        int i = base + e;
        int p = is64 ? words[2 * i] : words[i];
        if (p < 0) p = 0;
        local_pos[e] = p;
        g_pos[i] = p;
        if (p == 0) run = i;
    }
    chunk_last[tid] = run;
    __syncthreads();
    if (tid == 0) {
        int m = -1;
        for (int t = 0; t < 256; t++) {
            int c = chunk_last[t];
            chunk_last[t] = m;
            m = max(m, c);
        }
    }
    __syncthreads();
    int m = chunk_last[tid];
    #pragma unroll
    for (int e = 0; e < 8; e++) {
        int i = base + e;
        if (local_pos[e] == 0) m = i;
        g_segstart[i] = max(m, 0);
    }
}

// ---------------- fp32 -> bf16 hi/lo (row-major, vectorized) ----------------
__global__ void split_rowmajor(const float4* __restrict__ X,
                               __nv_bfloat162* __restrict__ Hh,
                               __nv_bfloat162* __restrict__ Hl, int n4) {
    int i = blockIdx.x * blockDim.x + threadIdx.x;
    if (i >= n4) return;
    float4 v = X[i];
    __nv_bfloat16 hx = __float2bfloat16(v.x);
    __nv_bfloat16 hy = __float2bfloat16(v.y);
    __nv_bfloat16 hz = __float2bfloat16(v.z);
    __nv_bfloat16 hw = __float2bfloat16(v.w);
    Hh[2 * i]     = __nv_bfloat162(hx, hy);
    Hh[2 * i + 1] = __nv_bfloat162(hz, hw);
    __nv_bfloat16 lx = __float2bfloat16(v.x - __bfloat162float(hx));
    __nv_bfloat16 ly = __float2bfloat16(v.y - __bfloat162float(hy));
    __nv_bfloat16 lz = __float2bfloat16(v.z - __bfloat162float(hz));
    __nv_bfloat16 lw = __float2bfloat16(v.w - __bfloat162float(hw));
    Hl[2 * i]     = __nv_bfloat162(lx, ly);
    Hl[2 * i + 1] = __nv_bfloat162(lz, lw);
}

// ---------------- fp32 W[K][N] -> bf16 hi/lo W^T [N][K] ----------------
__global__ void split_transpose(const float* __restrict__ W,
                                __nv_bfloat16* __restrict__ Th,
                                __nv_bfloat16* __restrict__ Tl, int K, int N) {
    __shared__ float t[32][33];
    int n0 = blockIdx.x * 32, k0 = blockIdx.y * 32;
    int tx = threadIdx.x, ty = threadIdx.y;   // (32, 8)
    #pragma unroll
    for (int i = 0; i < 32; i += 8)
        t[ty + i][tx] = W[(size_t)(k0 + ty + i) * N + n0 + tx];
    __syncthreads();
    #pragma unroll
    for (int i = 0; i < 32; i += 8) {
        float v = t[tx][ty + i];
        __nv_bfloat16 h = __float2bfloat16(v);
        float lo = v - __bfloat162float(h);
        size_t o = (size_t)(n0 + ty + i) * K + k0 + tx;
        Th[o] = h;
        Tl[o] = __float2bfloat16(lo);
    }
}

// ====== HMMA GEMM v2: C[M,N](f32) = A * B^T, bf16 hi/lo 3-term split =========
// A: [M][K] K-major; B: [N][K] K-major. CTA 128x128, BK=64, 8 warps m32xn64.
// smem stage: Ah[128][72] | Al | Bh[128][72] | Bl  (18432 B each, 144 B stride)
#define G_STRIDE 72
#define G_ARR    18432u
#define G_STAGE  73728u

__global__ __launch_bounds__(256, 1)
void gemm_mma2(const __nv_bfloat16* __restrict__ Ah, const __nv_bfloat16* __restrict__ Al,
               const __nv_bfloat16* __restrict__ Bh, const __nv_bfloat16* __restrict__ Bl,
               const float* __restrict__ bias, float* __restrict__ C,
               int M, int N, int K)
{
    extern __shared__ char dsm[];
    uint32_t sb = smem_u32(dsm);

    int tid = threadIdx.x, wid = tid >> 5, lane = tid & 31;
    int bx = blockIdx.x, by = blockIdx.y;
    int wm = (wid >> 1) * 32;       // warp M offset (0,32,64,96)
    int wn = (wid & 1) * 64;        // warp N offset (0,64)

    size_t arow0 = (size_t)by * 128;
    size_t brow0 = (size_t)bx * 128;

    int a_row = lane & 15;
    int a_k8  = lane >> 4;
    int b_row = (lane & 7) + ((lane >> 4) << 3);
    int b_k8  = (lane >> 3) & 1;

    // per-thread load coords: 1024 16B chunks per array per stage, 4/thread
    int lr = tid >> 3;              // row 0..127 (over 4 u-steps: tid+u*256)
    int lc = tid & 7;               // chunk-in-row

    float acc[2][8][4];
    #pragma unroll
    for (int i = 0; i < 2; i++)
        #pragma unroll
        for (int j = 0; j < 8; j++)
            #pragma unroll
            for (int e = 0; e < 4; e++) acc[i][j][e] = 0.f;

    int nchunks = K >> 6;

    auto prefetch = [&](int kc, int stg) {
        int koff = kc << 6;
        uint32_t st = sb + (uint32_t)stg * G_STAGE;
        #pragma unroll
        for (int u = 0; u < 4; u++) {
            int r = lr + u * 32;
            uint32_t so = (uint32_t)(r * 144 + lc * 16);
            CP_ASYNC16(st +              so, Ah + (arow0 + r) * (size_t)K + koff + lc * 8);
            CP_ASYNC16(st + G_ARR      + so, Al + (arow0 + r) * (size_t)K + koff + lc * 8);
            CP_ASYNC16(st + 2 * G_ARR  + so, Bh + (brow0 + r) * (size_t)K + koff + lc * 8);
            CP_ASYNC16(st + 3 * G_ARR  + so, Bl + (brow0 + r) * (size_t)K + koff + lc * 8);
        }
    };

    prefetch(0, 0);
    asm volatile("cp.async.commit_group;\n" ::: "memory");

    for (int kc = 0; kc < nchunks; kc++) {
        int stg = kc & 1;
        if (kc + 1 < nchunks) {
            prefetch(kc + 1, stg ^ 1);
            asm volatile("cp.async.commit_group;\n" ::: "memory");
            asm volatile("cp.async.wait_group 1;\n" ::: "memory");
        } else {
            asm volatile("cp.async.wait_group 0;\n" ::: "memory");
        }
        __syncthreads();
        uint32_t stb = sb + (uint32_t)stg * G_STAGE;

        #pragma unroll
        for (int ds = 0; ds < 4; ds++) {
            uint32_t ahf[2][4], alf[2][4];
            #pragma unroll
            for (int mi = 0; mi < 2; mi++) {
                uint32_t off = (uint32_t)((wm + mi * 16 + a_row) * G_STRIDE + ds * 16 + a_k8 * 8) * 2;
                ldmatrix_x4(ahf[mi], stb + off);
                ldmatrix_x4(alf[mi], stb + G_ARR + off);
            }
            #pragma unroll
            for (int nb = 0; nb < 4; nb++) {
                uint32_t boff = (uint32_t)((wn + nb * 16 + b_row) * G_STRIDE + ds * 16 + b_k8 * 8) * 2;
                uint32_t bhf[4], blf[4];
                ldmatrix_x4(bhf, stb + 2 * G_ARR + boff);
                ldmatrix_x4(blf, stb + 3 * G_ARR + boff);
                #pragma unroll
                for (int mi = 0; mi < 2; mi++) {
                    mma_bf16(acc[mi][2 * nb],     ahf[mi], bhf[0], bhf[1]);
                    mma_bf16(acc[mi][2 * nb],     ahf[mi], blf[0], blf[1]);
                    mma_bf16(acc[mi][2 * nb],     alf[mi], bhf[0], bhf[1]);
                    mma_bf16(acc[mi][2 * nb + 1], ahf[mi], bhf[2], bhf[3]);
                    mma_bf16(acc[mi][2 * nb + 1], ahf[mi], blf[2], blf[3]);
                    mma_bf16(acc[mi][2 * nb + 1], alf[mi], bhf[2], bhf[3]);
                }
            }
        }
        __syncthreads();
    }

    // epilogue
    int trow = lane >> 2;
    int tcol = (lane & 3) * 2;
    #pragma unroll
    for (int mi = 0; mi < 2; mi++) {
        #pragma unroll
        for (int hh = 0; hh < 2; hh++) {
            size_t row = arow0 + wm + mi * 16 + trow + hh * 8;
            float* crow = C + row * (size_t)N + brow0 + wn;
            #pragma unroll
            for (int nj = 0; nj < 8; nj++) {
                int col = nj * 8 + tcol;
                float2 o;
                o.x = acc[mi][nj][2 * hh];
                o.y = acc[mi][nj][2 * hh + 1];
                if (bias) {
                    o.x += bias[brow0 + wn + col];
                    o.y += bias[brow0 + wn + col + 1];
                }
                *(float2*)(crow + col) = o;
            }
        }
    }
}

// ---------------- RoPE + split into bf16 hi/lo head-major q/k, transposed v ----------------
__global__ void rope_split_kernel() {
    const int NQ = SEQ * NH * (HD / 2);
    const int NK = SEQ * NKV * (HD / 2);
    const int NV = SEQ * NKV * (HD / 4);
    int idx = blockIdx.x * blockDim.x + threadIdx.x;
    if (idx < NQ) {
        int s   = idx / (NH * (HD / 2));
        int rem = idx % (NH * (HD / 2));
        int h = rem >> 6, j = rem & 63;
        float freq = (float)g_pos[s] * g_invf[j];
        float sn, cs;
        sincosf(freq, &sn, &cs);
        const float* row = g_qkv + (size_t)s * QKVN + h * HD + 2 * j;
        float x1 = row[0], x2 = row[1];
        const float qscale = 0.08838834764831845f;
        float re = (x1 * cs - x2 * sn) * qscale;
        float im = (x1 * sn + x2 * cs) * qscale;
        size_t off = ((size_t)h * SEQ + s) * HD + 2 * j;
        __nv_bfloat16 hre = __float2bfloat16(re), him = __float2bfloat16(im);
        __nv_bfloat162 hp; hp.x = hre; hp.y = him;
        *(__nv_bfloat162*)(g_qh + off) = hp;
        __nv_bfloat162 lp;
        lp.x = __float2bfloat16(re - __bfloat162float(hre));
        lp.y = __float2bfloat16(im - __bfloat162float(him));
        *(__nv_bfloat162*)(g_ql + off) = lp;
        return;
    }
    idx -= NQ;
    if (idx < NK) {
        int s   = idx / (NKV * (HD / 2));
        int rem = idx % (NKV * (HD / 2));
        int h = rem >> 6, j = rem & 63;
        float freq = (float)g_pos[s] * g_invf[j];
        float sn, cs;
        sincosf(freq, &sn, &cs);
        const float* row = g_qkv + (size_t)s * QKVN + QSZ + h * HD + 2 * j;
        float x1 = row[0], x2 = row[1];
        float re = x1 * cs - x2 * sn;
        float im = x1 * sn + x2 * cs;
        size_t off = ((size_t)h * SEQ + s) * HD + 2 * j;
        __nv_bfloat16 hre = __float2bfloat16(re), him = __float2bfloat16(im);
        __nv_bfloat162 hp; hp.x = hre; hp.y = him;
        *(__nv_bfloat162*)(g_kh + off) = hp;
        __nv_bfloat162 lp;
        lp.x = __float2bfloat16(re - __bfloat162float(hre));
        lp.y = __float2bfloat16(im - __bfloat162float(him));
        *(__nv_bfloat162*)(g_kl + off) = lp;
        return;
    }
    idx -= NK;
    if (idx < NV) {
        int s = idx / (KVSZ / 4);
        int w = idx % (KVSZ / 4);
        int h = w >> 5;
        int d = (w * 4) & (HD - 1);
        float4 v = *(const float4*)(g_qkv + (size_t)s * QKVN + QSZ + KVSZ + w * 4);
        float vv[4] = {v.x, v.y, v.z, v.w};
        #pragma unroll
        for (int e = 0; e < 4; e++) {
            size_t off = ((size_t)h * HD + d + e) * SEQ + s;
            __nv_bfloat16 hb = __float2bfloat16(vv[e]);
            g_vTh[off] = hb;
            g_vTl[off] = __float2bfloat16(vv[e] - __bfloat162float(hb));
        }
    }
}

// ---------------- flash attention via HMMA (bf16 hi/lo 3-term) ----------------
#define FA_QH    0u
#define FA_QL    34816u
#define FA_ST    69632u
#define FA_STG   71680u
#define FA_KH    0u
#define FA_KL    17408u
#define FA_VH    34816u
#define FA_VL    53248u
#define FA_TOTAL 212992

__global__ __launch_bounds__(256, 1) void flash_mma_kernel() {
    extern __shared__ char sm8[];
    uint32_t sb = smem_u32(sm8);
    __shared__ int s_ktmin;

    int tid = threadIdx.x, wid = tid >> 5, lane = tid & 31;
    int qt = gridDim.x - 1 - blockIdx.x;   // heavy tiles first
    int h = blockIdx.y, kvh = h >> 3;
    int q0 = qt * 128;
    int wm = wid * 16;

    int a_row = lane & 15;
    int a_k8  = lane >> 4;
    int b_row = (lane & 7) + ((lane >> 4) << 3);
    int b_k8  = (lane >> 3) & 1;
    uint32_t q_off = (uint32_t)((wm + a_row) * 136 + a_k8 * 8) * 2;

    {
        const char* qh = (const char*)(g_qh + ((size_t)h * SEQ + q0) * HD);
        const char* ql = (const char*)(g_ql + ((size_t)h * SEQ + q0) * HD);
        #pragma unroll
        for (int u = 0; u < 8; u++) {
            int c = tid + u * 256;
            int r = c >> 4, cc = c & 15;
            CP_ASYNC16(sb + FA_QH + r * 272 + cc * 16, qh + r * 256 + cc * 16);
            CP_ASYNC16(sb + FA_QL + r * 272 + cc * 16, ql + r * 256 + cc * 16);
        }
    }
    if (tid == 0) {
        int mn = 0x7fffffff;
        for (int r = 0; r < 128; r++) mn = min(mn, g_segstart[q0 + r]);
        s_ktmin = mn >> 6;
    }

    int sg1 = q0 + wm + (lane >> 2);
    int sg2 = sg1 + 8;
    int ts1 = g_segstart[sg1], ts2 = g_segstart[sg2];

    float o[16][4];
    #pragma unroll
    for (int i = 0; i < 16; i++)
        #pragma unroll
        for (int e = 0; e < 4; e++) o[i][e] = 0.f;
    float m1 = -1e30f, m2 = -1e30f, l1 = 0.f, l2 = 0.f;

    __syncthreads();
    int ktmin = s_ktmin;
    int ktmax = (q0 + 127) >> 6;

    auto prefetch_tile = [&](int kt, int stg) {
        uint32_t st = sb + FA_ST + (uint32_t)stg * FA_STG;
        const char* kh = (const char*)(g_kh + ((size_t)kvh * SEQ + kt * 64) * HD);
        const char* kl = (const char*)(g_kl + ((size_t)kvh * SEQ + kt * 64) * HD);
        const char* vh = (const char*)(g_vTh + (size_t)kvh * HD * SEQ + kt * 64);
        const char* vl = (const char*)(g_vTl + (size_t)kvh * HD * SEQ + kt * 64);
        #pragma unroll
        for (int u = 0; u < 4; u++) {
            int c = tid + u * 256;
            int r = c >> 4, cc = c & 15;
            CP_ASYNC16(st + FA_KH + r * 272 + cc * 16, kh + r * 256 + cc * 16);
            CP_ASYNC16(st + FA_KL + r * 272 + cc * 16, kl + r * 256 + cc * 16);
            int vr = c >> 3, vc = c & 7;
            CP_ASYNC16(st + FA_VH + vr * 144 + vc * 16, vh + (size_t)vr * 4096 + vc * 16);
            CP_ASYNC16(st + FA_VL + vr * 144 + vc * 16, vl + (size_t)vr * 4096 + vc * 16);
        }
    };

    prefetch_tile(ktmin, 0);
    asm volatile("cp.async.commit_group;\n" ::: "memory");

    for (int kt = ktmin; kt <= ktmax; kt++) {
        int stg = (kt - ktmin) & 1;
        if (kt < ktmax) {
            prefetch_tile(kt + 1, stg ^ 1);
            asm volatile("cp.async.commit_group;\n" ::: "memory");
            asm volatile("cp.async.wait_group 1;\n" ::: "memory");
        } else {
            asm volatile("cp.async.wait_group 0;\n" ::: "memory");
        }
        __syncthreads();
        uint32_t stb = sb + FA_ST + (uint32_t)stg * FA_STG;

        float s[8][4];
        #pragma unroll
        for (int f = 0; f < 8; f++)
            #pragma unroll
            for (int e = 0; e < 4; e++) s[f][e] = 0.f;

        #pragma unroll
        for (int ds = 0; ds < 8; ds++) {
            uint32_t qhf[4], qlf[4];
            ldmatrix_x4(qhf, sb + FA_QH + q_off + ds * 32);
            ldmatrix_x4(qlf, sb + FA_QL + q_off + ds * 32);
            #pragma unroll
            for (int nb = 0; nb < 4; nb++) {
                uint32_t koff = (uint32_t)((nb * 16 + b_row) * 136 + ds * 16 + b_k8 * 8) * 2;
                uint32_t khf[4], klf[4];
                ldmatrix_x4(khf, stb + FA_KH + koff);
                ldmatrix_x4(klf, stb + FA_KL + koff);
                mma_bf16(s[2 * nb],     qhf, khf[0], khf[1]);
                mma_bf16(s[2 * nb],     qhf, klf[0], klf[1]);
                mma_bf16(s[2 * nb],     qlf, khf[0], khf[1]);
                mma_bf16(s[2 * nb + 1], qhf, khf[2], khf[3]);
                mma_bf16(s[2 * nb + 1], qhf, klf[2], klf[3]);
                mma_bf16(s[2 * nb + 1], qlf, khf[2], khf[3]);
            }
        }

        int colb = kt * 64 + (lane & 3) * 2;
        #pragma unroll
        for (int f = 0; f < 8; f++) {
            int t0 = colb + f * 8, t1 = t0 + 1;
            if (t0 > sg1 || t0 < ts1) s[f][0] = -1e30f;
            if (t1 > sg1 || t1 < ts1) s[f][1] = -1e30f;
            if (t0 > sg2 || t0 < ts2) s[f][2] = -1e30f;
            if (t1 > sg2 || t1 < ts2) s[f][3] = -1e30f;
        }

        float mx1 = -1e30f, mx2 = -1e30f;
        #pragma unroll
        for (int f = 0; f < 8; f++) {
            mx1 = fmaxf(mx1, fmaxf(s[f][0], s[f][1]));
            mx2 = fmaxf(mx2, fmaxf(s[f][2], s[f][3]));
        }
        mx1 = fmaxf(mx1, __shfl_xor_sync(0xffffffffu, mx1, 1));
        mx1 = fmaxf(mx1, __shfl_xor_sync(0xffffffffu, mx1, 2));
        mx2 = fmaxf(mx2, __shfl_xor_sync(0xffffffffu, mx2, 1));
        mx2 = fmaxf(mx2, __shfl_xor_sync(0xffffffffu, mx2, 2));
        float mn1 = fmaxf(m1, mx1), mn2 = fmaxf(m2, mx2);
        float a1 = __expf(m1 - mn1), a2 = __expf(m2 - mn2);
        m1 = mn1; m2 = mn2;

        float sum1 = 0.f, sum2 = 0.f;
        #pragma unroll
        for (int f = 0; f < 8; f++) {
            s[f][0] = __expf(s[f][0] - mn1);
            s[f][1] = __expf(s[f][1] - mn1);
            s[f][2] = __expf(s[f][2] - mn2);
            s[f][3] = __expf(s[f][3] - mn2);
            sum1 += s[f][0] + s[f][1];
            sum2 += s[f][2] + s[f][3];
        }
        sum1 += __shfl_xor_sync(0xffffffffu, sum1, 1);
        sum1 += __shfl_xor_sync(0xffffffffu, sum1, 2);
        sum2 += __shfl_xor_sync(0xffffffffu, sum2, 1);
        sum2 += __shfl_xor_sync(0xffffffffu, sum2, 2);
        l1 = l1 * a1 + sum1;
        l2 = l2 * a2 + sum2;

        #pragma unroll
        for (int i = 0; i < 16; i++) {
            o[i][0] *= a1; o[i][1] *= a1;
            o[i][2] *= a2; o[i][3] *= a2;
        }

        #pragma unroll
        for (int kk = 0; kk < 4; kk++) {
            float p0 = s[2 * kk][0],     p1 = s[2 * kk][1];
            float p2 = s[2 * kk][2],     p3 = s[2 * kk][3];
            float p4 = s[2 * kk + 1][0], p5 = s[2 * kk + 1][1];
            float p6 = s[2 * kk + 1][2], p7 = s[2 * kk + 1][3];
            uint32_t ph[4], pl[4];
            ph[0] = pack_bf16(p0, p1);
            ph[1] = pack_bf16(p2, p3);
            ph[2] = pack_bf16(p4, p5);
            ph[3] = pack_bf16(p6, p7);
            pl[0] = pack_bf16(p0 - __bfloat162float(__float2bfloat16(p0)),
                              p1 - __bfloat162float(__float2bfloat16(p1)));
            pl[1] = pack_bf16(p2 - __bfloat162float(__float2bfloat16(p2)),
                              p3 - __bfloat162float(__float2bfloat16(p3)));
            pl[2] = pack_bf16(p4 - __bfloat162float(__float2bfloat16(p4)),
                              p5 - __bfloat162float(__float2bfloat16(p5)));
            pl[3] = pack_bf16(p6 - __bfloat162float(__float2bfloat16(p6)),
                              p7 - __bfloat162float(__float2bfloat16(p7)));
            #pragma unroll
            for (int nb = 0; nb < 8; nb++) {
                uint32_t voff = (uint32_t)((nb * 16 + b_row) * 72 + kk * 16 + b_k8 * 8) * 2;
                uint32_t vhf[4], vlf[4];
                ldmatrix_x4(vhf, stb + FA_VH + voff);
                ldmatrix_x4(vlf, stb + FA_VL + voff);
                mma_bf16(o[2 * nb],     ph, vhf[0], vhf[1]);
                mma_bf16(o[2 * nb],     ph, vlf[0], vlf[1]);
                mma_bf16(o[2 * nb],     pl, vhf[0], vhf[1]);
                mma_bf16(o[2 * nb + 1], ph, vhf[2], vhf[3]);
                mma_bf16(o[2 * nb + 1], ph, vlf[2], vlf[3]);
                mma_bf16(o[2 * nb + 1], pl, vhf[2], vhf[3]);
            }
        }
        __syncthreads();
    }

    // ---- finalize: write attn output directly as bf16 hi/lo (O-proj A operand) ----
    float rn1 = (l1 > 0.f) ? 1.f / l1 : 0.f;
    float rn2 = (l2 > 0.f) ? 1.f / l2 : 0.f;
    int row1 = q0 + wm + (lane >> 2);
    int row2 = row1 + 8;
    #pragma unroll
    for (int nf = 0; nf < 16; nf++) {
        int col = h * HD + nf * 8 + (lane & 3) * 2;
        float a0 = o[nf][0] * rn1, a1v = o[nf][1] * rn1;
        float b0 = o[nf][2] * rn2, b1v = o[nf][3] * rn2;
        __nv_bfloat16 ha0 = __float2bfloat16(a0), ha1 = __float2bfloat16(a1v);
        __nv_bfloat16 hb0 = __float2bfloat16(b0), hb1 = __float2bfloat16(b1v);
        __nv_bfloat162 hv1; hv1.x = ha0; hv1.y = ha1;
        __nv_bfloat162 hv2; hv2.x = hb0; hv2.y = hb1;
        __nv_bfloat162 lv1, lv2;
        lv1.x = __float2bfloat16(a0 - __bfloat162float(ha0));
        lv1.y = __float2bfloat16(a1v - __bfloat162float(ha1));
        lv2.x = __float2bfloat16(b0 - __bfloat162float(hb0));
        lv2.y = __float2bfloat16(b1v - __bfloat162float(hb1));
        *(__nv_bfloat162*)&g_xh[(size_t)row1 * QSZ + col] = hv1;
        *(__nv_bfloat162*)&g_xl[(size_t)row1 * QSZ + col] = lv1;
        *(__nv_bfloat162*)&g_xh[(size_t)row2 * QSZ + col] = hv2;
        *(__nv_bfloat162*)&g_xl[(size_t)row2 * QSZ + col] = lv2;
    }
}

// ---------------- launch ----------------
extern "C" void kernel_launch(void* const* d_in, const int* in_sizes, int n_in,
                              void* d_out, int out_size) {
    const float* hidden = (const float*)d_in[0];
    const int*   posw   = (const int*)d_in[1];
    const float* w_qkv  = (const float*)d_in[2];
    const float* b_qkv  = (const float*)d_in[3];
    const float* w_o    = (const float*)d_in[4];
    float* out = (float*)d_out;

    void *p_qkv = nullptr, *p_xh = nullptr, *p_xl = nullptr;
    void *p_wqh = nullptr, *p_wql = nullptr, *p_woh = nullptr, *p_wol = nullptr;
    cudaGetSymbolAddress(&p_qkv, g_qkv);
    cudaGetSymbolAddress(&p_xh, g_xh);
    cudaGetSymbolAddress(&p_xl, g_xl);
    cudaGetSymbolAddress(&p_wqh, g_wqkvT_h);
    cudaGetSymbolAddress(&p_wql, g_wqkvT_l);
    cudaGetSymbolAddress(&p_woh, g_woT_h);
    cudaGetSymbolAddress(&p_wol, g_woT_l);

    const int gemm_smem = 2 * G_STAGE;   // 147456
    cudaFuncSetAttribute(gemm_mma2, cudaFuncAttributeMaxDynamicSharedMemorySize, gemm_smem);

    prep_kernel<<<1, 256>>>(posw);

    split_rowmajor<<<(SEQ * HID / 4 + 255) / 256, 256>>>(
        (const float4*)hidden, (__nv_bfloat162*)p_xh, (__nv_bfloat162*)p_xl, SEQ * HID / 4);
    split_transpose<<<dim3(QKVN / 32, HID / 32), dim3(32, 8)>>>(
        w_qkv, (__nv_bfloat16*)p_wqh, (__nv_bfloat16*)p_wql, HID, QKVN);
    split_transpose<<<dim3(HID / 32, QSZ / 32), dim3(32, 8)>>>(
        w_o, (__nv_bfloat16*)p_woh, (__nv_bfloat16*)p_wol, QSZ, HID);

    gemm_mma2<<<dim3(QKVN / 128, SEQ / 128), 256, gemm_smem>>>(
        (const __nv_bfloat16*)p_xh, (const __nv_bfloat16*)p_xl,
        (const __nv_bfloat16*)p_wqh, (const __nv_bfloat16*)p_wql,
        b_qkv, (float*)p_qkv, SEQ, QKVN, HID);

    int total = SEQ * NH * (HD / 2) + SEQ * NKV * (HD / 2) + SEQ * NKV * (HD / 4);
    rope_split_kernel<<<(total + 255) / 256, 256>>>();

    cudaFuncSetAttribute(flash_mma_kernel,
                         cudaFuncAttributeMaxDynamicSharedMemorySize, FA_TOTAL);
    flash_mma_kernel<<<dim3(SEQ / 128, NH), 256, FA_TOTAL>>>();

    gemm_mma2<<<dim3(HID / 128, SEQ / 128), 256, gemm_smem>>>(
        (const __nv_bfloat16*)p_xh, (const __nv_bfloat16*)p_xl,
        (const __nv_bfloat16*)p_woh, (const __nv_bfloat16*)p_wol,
        nullptr, out, SEQ, HID, QSZ);
}

// round 8
// speedup vs baseline: 4.7125x; 1.0112x over previous
#include <cuda_runtime.h>
#include <cuda_bf16.h>
#include <math.h>
#include <cstdint>

#define SEQ   2048
#define NH    16
#define NKV   2
#define HD    128
#define QSZ   (NH * HD)            // 2048
#define KVSZ  (NKV * HD)           // 256
#define QKVN  (QSZ + 2 * KVSZ)     // 2560
#define HID   2048
#define GROUPS (NH / NKV)          // 8

// ---------------- scratch (device globals; no allocs allowed) ----------------
__device__ float g_qkv[SEQ * QKVN];
__device__ int   g_pos[SEQ];
__device__ int   g_segstart[SEQ];
__device__ float g_invf[HD / 2];

// bf16 hi/lo split operands
__device__ __nv_bfloat16 g_qh[NH * SEQ * HD];     // [h][s][d]
__device__ __nv_bfloat16 g_ql[NH * SEQ * HD];
__device__ __nv_bfloat16 g_kh[NKV * SEQ * HD];    // [kvh][s][d]
__device__ __nv_bfloat16 g_kl[NKV * SEQ * HD];
__device__ __nv_bfloat16 g_vTh[NKV * HD * SEQ];   // [kvh][d][s]  (transposed)
__device__ __nv_bfloat16 g_vTl[NKV * HD * SEQ];
__device__ __nv_bfloat16 g_xh[SEQ * HID];         // activation hi (hidden, then attn out)
__device__ __nv_bfloat16 g_xl[SEQ * HID];
__device__ __nv_bfloat16 g_wqkvT_h[QKVN * HID];   // w_qkv^T  [2560][2048]
__device__ __nv_bfloat16 g_wqkvT_l[QKVN * HID];
__device__ __nv_bfloat16 g_woT_h[HID * QSZ];      // w_o^T    [2048][2048]
__device__ __nv_bfloat16 g_woT_l[HID * QSZ];

__device__ __forceinline__ uint32_t smem_u32(const void* p) {
    uint32_t a;
    asm("{ .reg .u64 t; cvta.to.shared.u64 t, %1; cvt.u32.u64 %0, t; }" : "=r"(a) : "l"(p));
    return a;
}

#define CP_ASYNC16(smem_addr, gptr) \
    asm volatile("cp.async.cg.shared.global [%0], [%1], 16;\n" \
        :: "r"((uint32_t)(smem_addr)), "l"(gptr))

__device__ __forceinline__ void ldmatrix_x4(uint32_t* r, uint32_t addr) {
    asm volatile("ldmatrix.sync.aligned.m8n8.x4.shared.b16 {%0,%1,%2,%3}, [%4];"
        : "=r"(r[0]), "=r"(r[1]), "=r"(r[2]), "=r"(r[3]) : "r"(addr));
}

__device__ __forceinline__ void mma_bf16(float* c, const uint32_t* a, uint32_t b0, uint32_t b1) {
    asm volatile(
        "mma.sync.aligned.m16n8k16.row.col.f32.bf16.bf16.f32 "
        "{%0,%1,%2,%3}, {%4,%5,%6,%7}, {%8,%9}, {%0,%1,%2,%3};"
        : "+f"(c[0]), "+f"(c[1]), "+f"(c[2]), "+f"(c[3])
        : "r"(a[0]), "r"(a[1]), "r"(a[2]), "r"(a[3]), "r"(b0), "r"(b1));
}

__device__ __forceinline__ uint32_t pack_bf16(float lo, float hi) {
    uint32_t r;
    asm("cvt.rn.bf16x2.f32 %0, %1, %2;" : "=r"(r) : "f"(hi), "f"(lo));
    return r;
}

// ---------------- prep: decode positions (int32/int64), seg scan ----------------
__global__ void prep_kernel(const int* __restrict__ words) {
    __shared__ int chunk_last[256];
    int tid = threadIdx.x;
    int is64 = (words[1] == 0) ? 1 : 0;

    if (tid < HD / 2) {
        g_invf[tid] = (float)(1.0 / pow(1.0e6, (double)(2 * tid) / (double)HD));
    }

    int base = tid * 8;
    int local_pos[8];
    int run = -1;
    #pragma unroll
    for (int e = 0; e < 8; e++) {
        int i = base + e;
        int p = is64 ? words[2 * i] : words[i];
        if (p < 0) p = 0;
        local_pos[e] = p;
        g_pos[i] = p;
        if (p == 0) run = i;
    }
    chunk_last[tid] = run;
    __syncthreads();
    if (tid == 0) {
        int m = -1;
        for (int t = 0; t < 256; t++) {
            int c = chunk_last[t];
            chunk_last[t] = m;
            m = max(m, c);
        }
    }
    __syncthreads();
    int m = chunk_last[tid];
    #pragma unroll
    for (int e = 0; e < 8; e++) {
        int i = base + e;
        if (local_pos[e] == 0) m = i;
        g_segstart[i] = max(m, 0);
    }
}

// ---------------- fp32 -> bf16 hi/lo (row-major, vectorized) ----------------
__global__ void split_rowmajor(const float4* __restrict__ X,
                               __nv_bfloat162* __restrict__ Hh,
                               __nv_bfloat162* __restrict__ Hl, int n4) {
    int i = blockIdx.x * blockDim.x + threadIdx.x;
    if (i >= n4) return;
    float4 v = X[i];
    __nv_bfloat16 hx = __float2bfloat16(v.x);
    __nv_bfloat16 hy = __float2bfloat16(v.y);
    __nv_bfloat16 hz = __float2bfloat16(v.z);
    __nv_bfloat16 hw = __float2bfloat16(v.w);
    Hh[2 * i]     = __nv_bfloat162(hx, hy);
    Hh[2 * i + 1] = __nv_bfloat162(hz, hw);
    __nv_bfloat16 lx = __float2bfloat16(v.x - __bfloat162float(hx));
    __nv_bfloat16 ly = __float2bfloat16(v.y - __bfloat162float(hy));
    __nv_bfloat16 lz = __float2bfloat16(v.z - __bfloat162float(hz));
    __nv_bfloat16 lw = __float2bfloat16(v.w - __bfloat162float(hw));
    Hl[2 * i]     = __nv_bfloat162(lx, ly);
    Hl[2 * i + 1] = __nv_bfloat162(lz, lw);
}

// ---------------- fp32 W[K][N] -> bf16 hi/lo W^T [N][K] ----------------
__global__ void split_transpose(const float* __restrict__ W,
                                __nv_bfloat16* __restrict__ Th,
                                __nv_bfloat16* __restrict__ Tl, int K, int N) {
    __shared__ float t[32][33];
    int n0 = blockIdx.x * 32, k0 = blockIdx.y * 32;
    int tx = threadIdx.x, ty = threadIdx.y;   // (32, 8)
    #pragma unroll
    for (int i = 0; i < 32; i += 8)
        t[ty + i][tx] = W[(size_t)(k0 + ty + i) * N + n0 + tx];
    __syncthreads();
    #pragma unroll
    for (int i = 0; i < 32; i += 8) {
        float v = t[tx][ty + i];
        __nv_bfloat16 h = __float2bfloat16(v);
        float lo = v - __bfloat162float(h);
        size_t o = (size_t)(n0 + ty + i) * K + k0 + tx;
        Th[o] = h;
        Tl[o] = __float2bfloat16(lo);
    }
}

// ====== HMMA GEMM v3: C[M,N](f32) = A * B^T, bf16 hi/lo 3-term split =========
// A: [M][K] K-major; B: [N][K] K-major. CTA 128x128, BK=32, 8 warps m32xn64.
// 2 CTAs/SM: stage = Ah[128][40el] | Al | Bh | Bl  (10240 B each, 80 B stride)
#define G_STRIDE 40
#define G_ARR    10240u
#define G_STAGE  40960u

__global__ __launch_bounds__(256, 2)
void gemm_mma3(const __nv_bfloat16* __restrict__ Ah, const __nv_bfloat16* __restrict__ Al,
               const __nv_bfloat16* __restrict__ Bh, const __nv_bfloat16* __restrict__ Bl,
               const float* __restrict__ bias, float* __restrict__ C,
               int M, int N, int K)
{
    extern __shared__ char dsm[];
    uint32_t sb = smem_u32(dsm);

    int tid = threadIdx.x, wid = tid >> 5, lane = tid & 31;
    int bx = blockIdx.x, by = blockIdx.y;
    int wm = (wid >> 1) * 32;       // warp M offset (0,32,64,96)
    int wn = (wid & 1) * 64;        // warp N offset (0,64)

    size_t arow0 = (size_t)by * 128;
    size_t brow0 = (size_t)bx * 128;

    int a_row = lane & 15;
    int a_k8  = lane >> 4;
    int b_row = (lane & 7) + ((lane >> 4) << 3);
    int b_k8  = (lane >> 3) & 1;

    // per-thread load coords: 512 16B chunks per array per stage, 2/thread
    float acc[2][8][4];
    #pragma unroll
    for (int i = 0; i < 2; i++)
        #pragma unroll
        for (int j = 0; j < 8; j++)
            #pragma unroll
            for (int e = 0; e < 4; e++) acc[i][j][e] = 0.f;

    int nchunks = K >> 5;

    auto prefetch = [&](int kc, int stg) {
        int koff = kc << 5;
        uint32_t st = sb + (uint32_t)stg * G_STAGE;
        #pragma unroll
        for (int u = 0; u < 2; u++) {
            int c = tid + u * 256;
            int r = c >> 2, q = c & 3;
            uint32_t so = (uint32_t)(r * 80 + q * 16);
            CP_ASYNC16(st +             so, Ah + (arow0 + r) * (size_t)K + koff + q * 8);
            CP_ASYNC16(st + G_ARR     + so, Al + (arow0 + r) * (size_t)K + koff + q * 8);
            CP_ASYNC16(st + 2 * G_ARR + so, Bh + (brow0 + r) * (size_t)K + koff + q * 8);
            CP_ASYNC16(st + 3 * G_ARR + so, Bl + (brow0 + r) * (size_t)K + koff + q * 8);
        }
    };

    prefetch(0, 0);
    asm volatile("cp.async.commit_group;\n" ::: "memory");

    for (int kc = 0; kc < nchunks; kc++) {
        int stg = kc & 1;
        if (kc + 1 < nchunks) {
            prefetch(kc + 1, stg ^ 1);
            asm volatile("cp.async.commit_group;\n" ::: "memory");
            asm volatile("cp.async.wait_group 1;\n" ::: "memory");
        } else {
            asm volatile("cp.async.wait_group 0;\n" ::: "memory");
        }
        __syncthreads();
        uint32_t stb = sb + (uint32_t)stg * G_STAGE;

        #pragma unroll
        for (int ds = 0; ds < 2; ds++) {
            uint32_t ahf[2][4], alf[2][4];
            #pragma unroll
            for (int mi = 0; mi < 2; mi++) {
                uint32_t off = (uint32_t)((wm + mi * 16 + a_row) * G_STRIDE + ds * 16 + a_k8 * 8) * 2;
                ldmatrix_x4(ahf[mi], stb + off);
                ldmatrix_x4(alf[mi], stb + G_ARR + off);
            }
            #pragma unroll
            for (int nb = 0; nb < 4; nb++) {
                uint32_t boff = (uint32_t)((wn + nb * 16 + b_row) * G_STRIDE + ds * 16 + b_k8 * 8) * 2;
                uint32_t bhf[4], blf[4];
                ldmatrix_x4(bhf, stb + 2 * G_ARR + boff);
                ldmatrix_x4(blf, stb + 3 * G_ARR + boff);
                #pragma unroll
                for (int mi = 0; mi < 2; mi++) {
                    mma_bf16(acc[mi][2 * nb],     ahf[mi], bhf[0], bhf[1]);
                    mma_bf16(acc[mi][2 * nb],     ahf[mi], blf[0], blf[1]);
                    mma_bf16(acc[mi][2 * nb],     alf[mi], bhf[0], bhf[1]);
                    mma_bf16(acc[mi][2 * nb + 1], ahf[mi], bhf[2], bhf[3]);
                    mma_bf16(acc[mi][2 * nb + 1], ahf[mi], blf[2], blf[3]);
                    mma_bf16(acc[mi][2 * nb + 1], alf[mi], bhf[2], bhf[3]);
                }
            }
        }
        __syncthreads();
    }

    // epilogue
    int trow = lane >> 2;
    int tcol = (lane & 3) * 2;
    #pragma unroll
    for (int mi = 0; mi < 2; mi++) {
        #pragma unroll
        for (int hh = 0; hh < 2; hh++) {
            size_t row = arow0 + wm + mi * 16 + trow + hh * 8;
            float* crow = C + row * (size_t)N + brow0 + wn;
            #pragma unroll
            for (int nj = 0; nj < 8; nj++) {
                int col = nj * 8 + tcol;
                float2 o;
                o.x = acc[mi][nj][2 * hh];
                o.y = acc[mi][nj][2 * hh + 1];
                if (bias) {
                    o.x += bias[brow0 + wn + col];
                    o.y += bias[brow0 + wn + col + 1];
                }
                *(float2*)(crow + col) = o;
            }
        }
    }
}

// ---------------- RoPE + split into bf16 hi/lo head-major q/k, transposed v ----------------
__global__ void rope_split_kernel() {
    const int NQ = SEQ * NH * (HD / 2);
    const int NK = SEQ * NKV * (HD / 2);
    const int NV = SEQ * NKV * (HD / 4);
    int idx = blockIdx.x * blockDim.x + threadIdx.x;
    if (idx < NQ) {
        int s   = idx / (NH * (HD / 2));
        int rem = idx % (NH * (HD / 2));
        int h = rem >> 6, j = rem & 63;
        float freq = (float)g_pos[s] * g_invf[j];
        float sn, cs;
        sincosf(freq, &sn, &cs);
        const float* row = g_qkv + (size_t)s * QKVN + h * HD + 2 * j;
        float x1 = row[0], x2 = row[1];
        const float qscale = 0.08838834764831845f;
        float re = (x1 * cs - x2 * sn) * qscale;
        float im = (x1 * sn + x2 * cs) * qscale;
        size_t off = ((size_t)h * SEQ + s) * HD + 2 * j;
        __nv_bfloat16 hre = __float2bfloat16(re), him = __float2bfloat16(im);
        __nv_bfloat162 hp; hp.x = hre; hp.y = him;
        *(__nv_bfloat162*)(g_qh + off) = hp;
        __nv_bfloat162 lp;
        lp.x = __float2bfloat16(re - __bfloat162float(hre));
        lp.y = __float2bfloat16(im - __bfloat162float(him));
        *(__nv_bfloat162*)(g_ql + off) = lp;
        return;
    }
    idx -= NQ;
    if (idx < NK) {
        int s   = idx / (NKV * (HD / 2));
        int rem = idx % (NKV * (HD / 2));
        int h = rem >> 6, j = rem & 63;
        float freq = (float)g_pos[s] * g_invf[j];
        float sn, cs;
        sincosf(freq, &sn, &cs);
        const float* row = g_qkv + (size_t)s * QKVN + QSZ + h * HD + 2 * j;
        float x1 = row[0], x2 = row[1];
        float re = x1 * cs - x2 * sn;
        float im = x1 * sn + x2 * cs;
        size_t off = ((size_t)h * SEQ + s) * HD + 2 * j;
        __nv_bfloat16 hre = __float2bfloat16(re), him = __float2bfloat16(im);
        __nv_bfloat162 hp; hp.x = hre; hp.y = him;
        *(__nv_bfloat162*)(g_kh + off) = hp;
        __nv_bfloat162 lp;
        lp.x = __float2bfloat16(re - __bfloat162float(hre));
        lp.y = __float2bfloat16(im - __bfloat162float(him));
        *(__nv_bfloat162*)(g_kl + off) = lp;
        return;
    }
    idx -= NK;
    if (idx < NV) {
        int s = idx / (KVSZ / 4);
        int w = idx % (KVSZ / 4);
        int h = w >> 5;
        int d = (w * 4) & (HD - 1);
        float4 v = *(const float4*)(g_qkv + (size_t)s * QKVN + QSZ + KVSZ + w * 4);
        float vv[4] = {v.x, v.y, v.z, v.w};
        #pragma unroll
        for (int e = 0; e < 4; e++) {
            size_t off = ((size_t)h * HD + d + e) * SEQ + s;
            __nv_bfloat16 hb = __float2bfloat16(vv[e]);
            g_vTh[off] = hb;
            g_vTl[off] = __float2bfloat16(vv[e] - __bfloat162float(hb));
        }
    }
}

// ---------------- flash attention via HMMA (bf16 hi/lo 3-term) ----------------
#define FA_QH    0u
#define FA_QL    34816u
#define FA_ST    69632u
#define FA_STG   71680u
#define FA_KH    0u
#define FA_KL    17408u
#define FA_VH    34816u
#define FA_VL    53248u
#define FA_TOTAL 212992

__global__ __launch_bounds__(256, 1) void flash_mma_kernel() {
    extern __shared__ char sm8[];
    uint32_t sb = smem_u32(sm8);
    __shared__ int s_ktmin;

    int tid = threadIdx.x, wid = tid >> 5, lane = tid & 31;
    int qt = gridDim.x - 1 - blockIdx.x;   // heavy tiles first
    int h = blockIdx.y, kvh = h >> 3;
    int q0 = qt * 128;
    int wm = wid * 16;

    int a_row = lane & 15;
    int a_k8  = lane >> 4;
    int b_row = (lane & 7) + ((lane >> 4) << 3);
    int b_k8  = (lane >> 3) & 1;
    uint32_t q_off = (uint32_t)((wm + a_row) * 136 + a_k8 * 8) * 2;

    {
        const char* qh = (const char*)(g_qh + ((size_t)h * SEQ + q0) * HD);
        const char* ql = (const char*)(g_ql + ((size_t)h * SEQ + q0) * HD);
        #pragma unroll
        for (int u = 0; u < 8; u++) {
            int c = tid + u * 256;
            int r = c >> 4, cc = c & 15;
            CP_ASYNC16(sb + FA_QH + r * 272 + cc * 16, qh + r * 256 + cc * 16);
            CP_ASYNC16(sb + FA_QL + r * 272 + cc * 16, ql + r * 256 + cc * 16);
        }
    }
    if (tid == 0) {
        int mn = 0x7fffffff;
        for (int r = 0; r < 128; r++) mn = min(mn, g_segstart[q0 + r]);
        s_ktmin = mn >> 6;
    }

    int sg1 = q0 + wm + (lane >> 2);
    int sg2 = sg1 + 8;
    int ts1 = g_segstart[sg1], ts2 = g_segstart[sg2];

    float o[16][4];
    #pragma unroll
    for (int i = 0; i < 16; i++)
        #pragma unroll
        for (int e = 0; e < 4; e++) o[i][e] = 0.f;
    float m1 = -1e30f, m2 = -1e30f, l1 = 0.f, l2 = 0.f;

    __syncthreads();
    int ktmin = s_ktmin;
    int ktmax = (q0 + 127) >> 6;

    auto prefetch_tile = [&](int kt, int stg) {
        uint32_t st = sb + FA_ST + (uint32_t)stg * FA_STG;
        const char* kh = (const char*)(g_kh + ((size_t)kvh * SEQ + kt * 64) * HD);
        const char* kl = (const char*)(g_kl + ((size_t)kvh * SEQ + kt * 64) * HD);
        const char* vh = (const char*)(g_vTh + (size_t)kvh * HD * SEQ + kt * 64);
        const char* vl = (const char*)(g_vTl + (size_t)kvh * HD * SEQ + kt * 64);
        #pragma unroll
        for (int u = 0; u < 4; u++) {
            int c = tid + u * 256;
            int r = c >> 4, cc = c & 15;
            CP_ASYNC16(st + FA_KH + r * 272 + cc * 16, kh + r * 256 + cc * 16);
            CP_ASYNC16(st + FA_KL + r * 272 + cc * 16, kl + r * 256 + cc * 16);
            int vr = c >> 3, vc = c & 7;
            CP_ASYNC16(st + FA_VH + vr * 144 + vc * 16, vh + (size_t)vr * 4096 + vc * 16);
            CP_ASYNC16(st + FA_VL + vr * 144 + vc * 16, vl + (size_t)vr * 4096 + vc * 16);
        }
    };

    prefetch_tile(ktmin, 0);
    asm volatile("cp.async.commit_group;\n" ::: "memory");

    for (int kt = ktmin; kt <= ktmax; kt++) {
        int stg = (kt - ktmin) & 1;
        if (kt < ktmax) {
            prefetch_tile(kt + 1, stg ^ 1);
            asm volatile("cp.async.commit_group;\n" ::: "memory");
            asm volatile("cp.async.wait_group 1;\n" ::: "memory");
        } else {
            asm volatile("cp.async.wait_group 0;\n" ::: "memory");
        }
        __syncthreads();
        uint32_t stb = sb + FA_ST + (uint32_t)stg * FA_STG;

        float s[8][4];
        #pragma unroll
        for (int f = 0; f < 8; f++)
            #pragma unroll
            for (int e = 0; e < 4; e++) s[f][e] = 0.f;

        #pragma unroll
        for (int ds = 0; ds < 8; ds++) {
            uint32_t qhf[4], qlf[4];
            ldmatrix_x4(qhf, sb + FA_QH + q_off + ds * 32);
            ldmatrix_x4(qlf, sb + FA_QL + q_off + ds * 32);
            #pragma unroll
            for (int nb = 0; nb < 4; nb++) {
                uint32_t koff = (uint32_t)((nb * 16 + b_row) * 136 + ds * 16 + b_k8 * 8) * 2;
                uint32_t khf[4], klf[4];
                ldmatrix_x4(khf, stb + FA_KH + koff);
                ldmatrix_x4(klf, stb + FA_KL + koff);
                mma_bf16(s[2 * nb],     qhf, khf[0], khf[1]);
                mma_bf16(s[2 * nb],     qhf, klf[0], klf[1]);
                mma_bf16(s[2 * nb],     qlf, khf[0], khf[1]);
                mma_bf16(s[2 * nb + 1], qhf, khf[2], khf[3]);
                mma_bf16(s[2 * nb + 1], qhf, klf[2], klf[3]);
                mma_bf16(s[2 * nb + 1], qlf, khf[2], khf[3]);
            }
        }

        int colb = kt * 64 + (lane & 3) * 2;
        #pragma unroll
        for (int f = 0; f < 8; f++) {
            int t0 = colb + f * 8, t1 = t0 + 1;
            if (t0 > sg1 || t0 < ts1) s[f][0] = -1e30f;
            if (t1 > sg1 || t1 < ts1) s[f][1] = -1e30f;
            if (t0 > sg2 || t0 < ts2) s[f][2] = -1e30f;
            if (t1 > sg2 || t1 < ts2) s[f][3] = -1e30f;
        }

        float mx1 = -1e30f, mx2 = -1e30f;
        #pragma unroll
        for (int f = 0; f < 8; f++) {
            mx1 = fmaxf(mx1, fmaxf(s[f][0], s[f][1]));
            mx2 = fmaxf(mx2, fmaxf(s[f][2], s[f][3]));
        }
        mx1 = fmaxf(mx1, __shfl_xor_sync(0xffffffffu, mx1, 1));
        mx1 = fmaxf(mx1, __shfl_xor_sync(0xffffffffu, mx1, 2));
        mx2 = fmaxf(mx2, __shfl_xor_sync(0xffffffffu, mx2, 1));
        mx2 = fmaxf(mx2, __shfl_xor_sync(0xffffffffu, mx2, 2));
        float mn1 = fmaxf(m1, mx1), mn2 = fmaxf(m2, mx2);
        float a1 = __expf(m1 - mn1), a2 = __expf(m2 - mn2);
        m1 = mn1; m2 = mn2;

        float sum1 = 0.f, sum2 = 0.f;
        #pragma unroll
        for (int f = 0; f < 8; f++) {
            s[f][0] = __expf(s[f][0] - mn1);
            s[f][1] = __expf(s[f][1] - mn1);
            s[f][2] = __expf(s[f][2] - mn2);
            s[f][3] = __expf(s[f][3] - mn2);
            sum1 += s[f][0] + s[f][1];
            sum2 += s[f][2] + s[f][3];
        }
        sum1 += __shfl_xor_sync(0xffffffffu, sum1, 1);
        sum1 += __shfl_xor_sync(0xffffffffu, sum1, 2);
        sum2 += __shfl_xor_sync(0xffffffffu, sum2, 1);
        sum2 += __shfl_xor_sync(0xffffffffu, sum2, 2);
        l1 = l1 * a1 + sum1;
        l2 = l2 * a2 + sum2;

        #pragma unroll
        for (int i = 0; i < 16; i++) {
            o[i][0] *= a1; o[i][1] *= a1;
            o[i][2] *= a2; o[i][3] *= a2;
        }

        #pragma unroll
        for (int kk = 0; kk < 4; kk++) {
            float p0 = s[2 * kk][0],     p1 = s[2 * kk][1];
            float p2 = s[2 * kk][2],     p3 = s[2 * kk][3];
            float p4 = s[2 * kk + 1][0], p5 = s[2 * kk + 1][1];
            float p6 = s[2 * kk + 1][2], p7 = s[2 * kk + 1][3];
            uint32_t ph[4], pl[4];
            ph[0] = pack_bf16(p0, p1);
            ph[1] = pack_bf16(p2, p3);
            ph[2] = pack_bf16(p4, p5);
            ph[3] = pack_bf16(p6, p7);
            pl[0] = pack_bf16(p0 - __bfloat162float(__float2bfloat16(p0)),
                              p1 - __bfloat162float(__float2bfloat16(p1)));
            pl[1] = pack_bf16(p2 - __bfloat162float(__float2bfloat16(p2)),
                              p3 - __bfloat162float(__float2bfloat16(p3)));
            pl[2] = pack_bf16(p4 - __bfloat162float(__float2bfloat16(p4)),
                              p5 - __bfloat162float(__float2bfloat16(p5)));
            pl[3] = pack_bf16(p6 - __bfloat162float(__float2bfloat16(p6)),
                              p7 - __bfloat162float(__float2bfloat16(p7)));
            #pragma unroll
            for (int nb = 0; nb < 8; nb++) {
                uint32_t voff = (uint32_t)((nb * 16 + b_row) * 72 + kk * 16 + b_k8 * 8) * 2;
                uint32_t vhf[4], vlf[4];
                ldmatrix_x4(vhf, stb + FA_VH + voff);
                ldmatrix_x4(vlf, stb + FA_VL + voff);
                mma_bf16(o[2 * nb],     ph, vhf[0], vhf[1]);
                mma_bf16(o[2 * nb],     ph, vlf[0], vlf[1]);
                mma_bf16(o[2 * nb],     pl, vhf[0], vhf[1]);
                mma_bf16(o[2 * nb + 1], ph, vhf[2], vhf[3]);
                mma_bf16(o[2 * nb + 1], ph, vlf[2], vlf[3]);
                mma_bf16(o[2 * nb + 1], pl, vhf[2], vhf[3]);
            }
        }
        __syncthreads();
    }

    // ---- finalize: write attn output directly as bf16 hi/lo (O-proj A operand) ----
    float rn1 = (l1 > 0.f) ? 1.f / l1 : 0.f;
    float rn2 = (l2 > 0.f) ? 1.f / l2 : 0.f;
    int row1 = q0 + wm + (lane >> 2);
    int row2 = row1 + 8;
    #pragma unroll
    for (int nf = 0; nf < 16; nf++) {
        int col = h * HD + nf * 8 + (lane & 3) * 2;
        float a0 = o[nf][0] * rn1, a1v = o[nf][1] * rn1;
        float b0 = o[nf][2] * rn2, b1v = o[nf][3] * rn2;
        __nv_bfloat16 ha0 = __float2bfloat16(a0), ha1 = __float2bfloat16(a1v);
        __nv_bfloat16 hb0 = __float2bfloat16(b0), hb1 = __float2bfloat16(b1v);
        __nv_bfloat162 hv1; hv1.x = ha0; hv1.y = ha1;
        __nv_bfloat162 hv2; hv2.x = hb0; hv2.y = hb1;
        __nv_bfloat162 lv1, lv2;
        lv1.x = __float2bfloat16(a0 - __bfloat162float(ha0));
        lv1.y = __float2bfloat16(a1v - __bfloat162float(ha1));
        lv2.x = __float2bfloat16(b0 - __bfloat162float(hb0));
        lv2.y = __float2bfloat16(b1v - __bfloat162float(hb1));
        *(__nv_bfloat162*)&g_xh[(size_t)row1 * QSZ + col] = hv1;
        *(__nv_bfloat162*)&g_xl[(size_t)row1 * QSZ + col] = lv1;
        *(__nv_bfloat162*)&g_xh[(size_t)row2 * QSZ + col] = hv2;
        *(__nv_bfloat162*)&g_xl[(size_t)row2 * QSZ + col] = lv2;
    }
}

// ---------------- launch ----------------
extern "C" void kernel_launch(void* const* d_in, const int* in_sizes, int n_in,
                              void* d_out, int out_size) {
    const float* hidden = (const float*)d_in[0];
    const int*   posw   = (const int*)d_in[1];
    const float* w_qkv  = (const float*)d_in[2];
    const float* b_qkv  = (const float*)d_in[3];
    const float* w_o    = (const float*)d_in[4];
    float* out = (float*)d_out;

    void *p_qkv = nullptr, *p_xh = nullptr, *p_xl = nullptr;
    void *p_wqh = nullptr, *p_wql = nullptr, *p_woh = nullptr, *p_wol = nullptr;
    cudaGetSymbolAddress(&p_qkv, g_qkv);
    cudaGetSymbolAddress(&p_xh, g_xh);
    cudaGetSymbolAddress(&p_xl, g_xl);
    cudaGetSymbolAddress(&p_wqh, g_wqkvT_h);
    cudaGetSymbolAddress(&p_wql, g_wqkvT_l);
    cudaGetSymbolAddress(&p_woh, g_woT_h);
    cudaGetSymbolAddress(&p_wol, g_woT_l);

    const int gemm_smem = 2 * G_STAGE;   // 81920
    cudaFuncSetAttribute(gemm_mma3, cudaFuncAttributeMaxDynamicSharedMemorySize, gemm_smem);

    prep_kernel<<<1, 256>>>(posw);

    split_rowmajor<<<(SEQ * HID / 4 + 255) / 256, 256>>>(
        (const float4*)hidden, (__nv_bfloat162*)p_xh, (__nv_bfloat162*)p_xl, SEQ * HID / 4);
    split_transpose<<<dim3(QKVN / 32, HID / 32), dim3(32, 8)>>>(
        w_qkv, (__nv_bfloat16*)p_wqh, (__nv_bfloat16*)p_wql, HID, QKVN);
    split_transpose<<<dim3(HID / 32, QSZ / 32), dim3(32, 8)>>>(
        w_o, (__nv_bfloat16*)p_woh, (__nv_bfloat16*)p_wol, QSZ, HID);

    gemm_mma3<<<dim3(QKVN / 128, SEQ / 128), 256, gemm_smem>>>(
        (const __nv_bfloat16*)p_xh, (const __nv_bfloat16*)p_xl,
        (const __nv_bfloat16*)p_wqh, (const __nv_bfloat16*)p_wql,
        b_qkv, (float*)p_qkv, SEQ, QKVN, HID);

    int total = SEQ * NH * (HD / 2) + SEQ * NKV * (HD / 2) + SEQ * NKV * (HD / 4);
    rope_split_kernel<<<(total + 255) / 256, 256>>>();

    cudaFuncSetAttribute(flash_mma_kernel,
                         cudaFuncAttributeMaxDynamicSharedMemorySize, FA_TOTAL);
    flash_mma_kernel<<<dim3(SEQ / 128, NH), 256, FA_TOTAL>>>();

    gemm_mma3<<<dim3(HID / 128, SEQ / 128), 256, gemm_smem>>>(
        (const __nv_bfloat16*)p_xh, (const __nv_bfloat16*)p_xl,
        (const __nv_bfloat16*)p_woh, (const __nv_bfloat16*)p_wol,
        nullptr, out, SEQ, HID, QSZ);
}